// round 3
// baseline (speedup 1.0000x reference)
#include <cuda_runtime.h>
#include <math_constants.h>

#define B_SZ 8
#define CIN  256
#define COUT 128
#define NTOK 4096

// ---- scratch (static device globals; no allocation) ----
__device__ float g_Q [B_SZ * NTOK * COUT];   // [b][n][d]
__device__ float g_K [B_SZ * NTOK * COUT];   // [b][m][d]
__device__ float g_Vt[B_SZ * NTOK * CIN];    // [b][m][c]
__device__ float g_Ot[B_SZ * NTOK * CIN];    // [b][n][c]

// ============================================================================
// Kernel 1: 1x1-conv projections  Q = p^T Wq + bq,  K = b^T Wk + bk
// grid (NTOK/32, B, 2), block 256.  Tile: 32 n x 128 d, c chunked by 64.
// ============================================================================
__global__ __launch_bounds__(256) void proj_kernel(
    const float* __restrict__ p, const float* __restrict__ bin,
    const float* __restrict__ Wq, const float* __restrict__ bq,
    const float* __restrict__ Wk, const float* __restrict__ bk)
{
    __shared__ float wst[64][129];   // wst[cc][d] = W[d][c0+cc]
    __shared__ float xs [64][36];    // xs[cc][n]  = X[c0+cc][n0+n]

    const int nt = blockIdx.x, bb = blockIdx.y, z = blockIdx.z;
    const float* X    = (z == 0) ? p  : bin;
    const float* W    = (z == 0) ? Wq : Wk;
    const float* bias = (z == 0) ? bq : bk;
    float*       Out  = (z == 0) ? g_Q : g_K;

    const int t   = threadIdx.x;
    const int d   = t & 127;        // output channel
    const int ng  = t >> 7;         // 0..1 -> n sub-block
    const int n0  = ng * 16;
    const int gn0 = nt * 32;

    float acc[16];
    const float bv = bias[d];
#pragma unroll
    for (int j = 0; j < 16; j++) acc[j] = bv;

    const float* Xb = X + (size_t)bb * CIN * NTOK;

    for (int c0 = 0; c0 < CIN; c0 += 64) {
        for (int e = t; e < 64 * 128; e += 256) {       // W chunk (coalesced read)
            int cc = e & 63, dd = e >> 6;
            wst[cc][dd] = W[dd * CIN + c0 + cc];
        }
        for (int e = t; e < 64 * 32; e += 256) {        // x chunk (coalesced read)
            int cc = e >> 5, nn = e & 31;
            xs[cc][nn] = Xb[(size_t)(c0 + cc) * NTOK + gn0 + nn];
        }
        __syncthreads();
#pragma unroll 8
        for (int cc = 0; cc < 64; cc++) {
            const float w = wst[cc][d];
            const float4* xr = (const float4*)&xs[cc][n0];
#pragma unroll
            for (int j4 = 0; j4 < 4; j4++) {
                float4 xv = xr[j4];
                acc[j4 * 4 + 0] += w * xv.x;
                acc[j4 * 4 + 1] += w * xv.y;
                acc[j4 * 4 + 2] += w * xv.z;
                acc[j4 * 4 + 3] += w * xv.w;
            }
        }
        __syncthreads();
    }

    float* Ob = Out + (size_t)bb * NTOK * COUT;
#pragma unroll
    for (int j = 0; j < 16; j++)                        // coalesced: lanes -> consecutive d
        Ob[(size_t)(gn0 + n0 + j) * COUT + d] = acc[j];
}

// ============================================================================
// Kernel 2: V transpose  g_Vt[b][n][c] = bin[b][c][n]
// grid (NTOK/32, CIN/32, B), block (32, 8)
// ============================================================================
__global__ __launch_bounds__(256) void transpose_v_kernel(const float* __restrict__ bin)
{
    __shared__ float tile[32][33];
    const int bb = blockIdx.z;
    const int c0 = blockIdx.y * 32;
    const int n0 = blockIdx.x * 32;
    const int tx = threadIdx.x, ty = threadIdx.y;

    const float* src = bin + (size_t)bb * CIN * NTOK;
#pragma unroll
    for (int k = 0; k < 4; k++)
        tile[ty + 8 * k][tx] = src[(size_t)(c0 + ty + 8 * k) * NTOK + n0 + tx];
    __syncthreads();
    float* dst = g_Vt + (size_t)bb * NTOK * CIN;
#pragma unroll
    for (int k = 0; k < 4; k++)
        dst[(size_t)(n0 + ty + 8 * k) * CIN + c0 + tx] = tile[tx][ty + 8 * k];
}

// ============================================================================
// Kernel 3: flash attention, fp32.
// grid (NTOK/64, B), block 256, dynamic smem 93440 B, 2 CTAs/SM.
// Each CTA: 64 queries; loop over key blocks of 32.
// Thread (ty=t/16, tx=t%16) owns q = 4*ty..+3 and c = 4*tx + {0,64,128,192}+0..3
// ============================================================================
#define QS_ROW 132
#define KS_ROW 132
#define VS_ROW 260
#define SS_ROW 68
#define ATTN_SMEM_FLOATS (64*QS_ROW + 32*KS_ROW + 32*VS_ROW + 32*SS_ROW + 192)

__global__ __launch_bounds__(256, 2) void attn_kernel()
{
    extern __shared__ float smf[];
    float* Qs     = smf;                    // [64][132]
    float* Ks     = Qs + 64 * QS_ROW;       // [32][132]
    float* Vs     = Ks + 32 * KS_ROW;       // [32][260]
    float* Ss     = Vs + 32 * VS_ROW;       // [32][68]  scores, k-major
    float* rmax   = Ss + 32 * SS_ROW;       // [64]
    float* rsum   = rmax + 64;              // [64]
    float* ralpha = rsum + 64;              // [64]

    const int t  = threadIdx.x;
    const int bb = blockIdx.y;
    const int n0 = blockIdx.x * 64;

    const float* Qg = g_Q  + ((size_t)bb * NTOK + n0) * COUT;
    const float* Kg = g_K  + (size_t)bb * NTOK * COUT;
    const float* Vg = g_Vt + (size_t)bb * NTOK * CIN;

    { // load Q tile (64 x 128), float4, coalesced
        const float4* Qg4 = (const float4*)Qg;
        for (int e = t; e < 64 * 32; e += 256) {
            int qq = e >> 5, dd4 = e & 31;
            *(float4*)&Qs[qq * QS_ROW + dd4 * 4] = Qg4[qq * 32 + dd4];
        }
    }
    if (t < 64) { rmax[t] = -CUDART_INF_F; rsum[t] = 0.f; }

    const int ty = t >> 4, tx = t & 15;
    const int q0 = ty * 4;
    const int sq = t >> 2, ssub = t & 3;    // softmax mapping: 4 threads per q row

    float o[4][16];
#pragma unroll
    for (int i = 0; i < 4; i++)
#pragma unroll
        for (int j = 0; j < 16; j++) o[i][j] = 0.f;

    for (int kb = 0; kb < NTOK / 32; kb++) {
        const int m0 = kb * 32;
        __syncthreads();                    // previous stage-3 done before overwrite

        { // load K tile (32x128) and V tile (32x256)
            const float4* Kg4 = (const float4*)(Kg + (size_t)m0 * COUT);
            for (int e = t; e < 32 * 32; e += 256) {
                int mm = e >> 5, dd4 = e & 31;
                *(float4*)&Ks[mm * KS_ROW + dd4 * 4] = Kg4[mm * 32 + dd4];
            }
            const float4* Vg4 = (const float4*)(Vg + (size_t)m0 * CIN);
            for (int e = t; e < 32 * 64; e += 256) {
                int mm = e >> 6, cc4 = e & 63;
                *(float4*)&Vs[mm * VS_ROW + cc4 * 4] = Vg4[mm * 64 + cc4];
            }
        }
        __syncthreads();

        // ---- stage 1: scores S[k][q], k in {tx, tx+16}, q in q0..q0+3 ----
        {
            float s[4][2];
#pragma unroll
            for (int i = 0; i < 4; i++) { s[i][0] = 0.f; s[i][1] = 0.f; }
#pragma unroll 4
            for (int dd = 0; dd < 128; dd += 4) {
                float4 kv0 = *(const float4*)&Ks[tx * KS_ROW + dd];
                float4 kv1 = *(const float4*)&Ks[(tx + 16) * KS_ROW + dd];
#pragma unroll
                for (int i = 0; i < 4; i++) {
                    float4 qv = *(const float4*)&Qs[(q0 + i) * QS_ROW + dd];
                    s[i][0] += qv.x * kv0.x + qv.y * kv0.y + qv.z * kv0.z + qv.w * kv0.w;
                    s[i][1] += qv.x * kv1.x + qv.y * kv1.y + qv.z * kv1.z + qv.w * kv1.w;
                }
            }
            float4 a0 = make_float4(s[0][0], s[1][0], s[2][0], s[3][0]);
            float4 a1 = make_float4(s[0][1], s[1][1], s[2][1], s[3][1]);
            *(float4*)&Ss[tx * SS_ROW + q0]        = a0;
            *(float4*)&Ss[(tx + 16) * SS_ROW + q0] = a1;
        }
        __syncthreads();

        // ---- stage 2: online softmax (4 threads per q row, 8 keys each) ----
        {
            float vals[8];
#pragma unroll
            for (int i = 0; i < 8; i++) vals[i] = Ss[(ssub * 8 + i) * SS_ROW + sq];
            float pm = vals[0];
#pragma unroll
            for (int i = 1; i < 8; i++) pm = fmaxf(pm, vals[i]);
            pm = fmaxf(pm, __shfl_xor_sync(0xffffffffu, pm, 1));
            pm = fmaxf(pm, __shfl_xor_sync(0xffffffffu, pm, 2));
            const float mold = rmax[sq];
            const float mnew = fmaxf(mold, pm);
            float psum = 0.f;
#pragma unroll
            for (int i = 0; i < 8; i++) {
                float e = __expf(vals[i] - mnew);
                Ss[(ssub * 8 + i) * SS_ROW + sq] = e;
                psum += e;
            }
            psum += __shfl_xor_sync(0xffffffffu, psum, 1);
            psum += __shfl_xor_sync(0xffffffffu, psum, 2);
            if (ssub == 0) {
                const float alpha = __expf(mold - mnew);   // exp(-inf)=0 on iter 0
                rsum[sq]   = rsum[sq] * alpha + psum;
                rmax[sq]   = mnew;
                ralpha[sq] = alpha;
            }
        }
        __syncthreads();

        // ---- stage 3: O = O*alpha + P @ V ----
        {
            float a0 = ralpha[q0], a1 = ralpha[q0 + 1], a2 = ralpha[q0 + 2], a3 = ralpha[q0 + 3];
#pragma unroll
            for (int j = 0; j < 16; j++) {
                o[0][j] *= a0; o[1][j] *= a1; o[2][j] *= a2; o[3][j] *= a3;
            }
#pragma unroll 2
            for (int mm = 0; mm < 32; mm++) {
                float4 pv = *(const float4*)&Ss[mm * SS_ROW + q0];
#pragma unroll
                for (int j4 = 0; j4 < 4; j4++) {
                    float4 vv = *(const float4*)&Vs[mm * VS_ROW + (tx << 2) + (j4 << 6)];
                    o[0][j4*4+0] += pv.x*vv.x; o[0][j4*4+1] += pv.x*vv.y;
                    o[0][j4*4+2] += pv.x*vv.z; o[0][j4*4+3] += pv.x*vv.w;
                    o[1][j4*4+0] += pv.y*vv.x; o[1][j4*4+1] += pv.y*vv.y;
                    o[1][j4*4+2] += pv.y*vv.z; o[1][j4*4+3] += pv.y*vv.w;
                    o[2][j4*4+0] += pv.z*vv.x; o[2][j4*4+1] += pv.z*vv.y;
                    o[2][j4*4+2] += pv.z*vv.z; o[2][j4*4+3] += pv.z*vv.w;
                    o[3][j4*4+0] += pv.w*vv.x; o[3][j4*4+1] += pv.w*vv.y;
                    o[3][j4*4+2] += pv.w*vv.z; o[3][j4*4+3] += pv.w*vv.w;
                }
            }
        }
    }
    __syncthreads();

    // epilogue: divide by row sum, write Ot[b][n][c] (coalesced float4)
    float inv[4];
#pragma unroll
    for (int i = 0; i < 4; i++) inv[i] = 1.0f / rsum[q0 + i];
    float* Og = g_Ot + ((size_t)bb * NTOK + n0) * CIN;
#pragma unroll
    for (int i = 0; i < 4; i++) {
#pragma unroll
        for (int j4 = 0; j4 < 4; j4++) {
            float4 w = make_float4(o[i][j4*4+0] * inv[i], o[i][j4*4+1] * inv[i],
                                   o[i][j4*4+2] * inv[i], o[i][j4*4+3] * inv[i]);
            *(float4*)&Og[(size_t)(q0 + i) * CIN + (tx << 2) + (j4 << 6)] = w;
        }
    }
}

// ============================================================================
// Kernel 4: O transpose  out[b][c][n] = g_Ot[b][n][c]
// grid (NTOK/32, CIN/32, B), block (32, 8)
// ============================================================================
__global__ __launch_bounds__(256) void transpose_o_kernel(float* __restrict__ out)
{
    __shared__ float tile[32][33];
    const int bb = blockIdx.z;
    const int c0 = blockIdx.y * 32;
    const int n0 = blockIdx.x * 32;
    const int tx = threadIdx.x, ty = threadIdx.y;

    const float* src = g_Ot + (size_t)bb * NTOK * CIN;
#pragma unroll
    for (int k = 0; k < 4; k++)
        tile[ty + 8 * k][tx] = src[(size_t)(n0 + ty + 8 * k) * CIN + c0 + tx];
    __syncthreads();
    float* dst = out + (size_t)bb * CIN * NTOK;
#pragma unroll
    for (int k = 0; k < 4; k++)
        dst[(size_t)(c0 + ty + 8 * k) * NTOK + n0 + tx] = tile[tx][ty + 8 * k];
}

// ============================================================================
extern "C" void kernel_launch(void* const* d_in, const int* in_sizes, int n_in,
                              void* d_out, int out_size)
{
    const float* p   = (const float*)d_in[0];
    const float* bin = (const float*)d_in[1];
    const float* Wq  = (const float*)d_in[2];
    const float* bq  = (const float*)d_in[3];
    const float* Wk  = (const float*)d_in[4];
    const float* bk  = (const float*)d_in[5];
    float* out = (float*)d_out;

    cudaFuncSetAttribute(attn_kernel, cudaFuncAttributeMaxDynamicSharedMemorySize,
                         (int)(ATTN_SMEM_FLOATS * sizeof(float)));

    proj_kernel       <<<dim3(NTOK / 32, B_SZ, 2), 256>>>(p, bin, Wq, bq, Wk, bk);
    transpose_v_kernel<<<dim3(NTOK / 32, CIN / 32, B_SZ), dim3(32, 8)>>>(bin);
    attn_kernel       <<<dim3(NTOK / 64, B_SZ), 256,
                         ATTN_SMEM_FLOATS * sizeof(float)>>>();
    transpose_o_kernel<<<dim3(NTOK / 32, CIN / 32, B_SZ), dim3(32, 8)>>>(out);
}

// round 7
// speedup vs baseline: 1.0032x; 1.0032x over previous
#include <cuda_runtime.h>
#include <math_constants.h>

#define B_SZ 8
#define CIN  256
#define COUT 128
#define NTOK 4096

// ---- scratch (static device globals; no allocation) ----
__device__ float g_Q [B_SZ * NTOK * COUT];   // [b][n][d]
__device__ float g_K [B_SZ * NTOK * COUT];   // [b][m][d]
__device__ float g_Vt[B_SZ * NTOK * CIN];    // [b][m][c]
__device__ float g_Ot[B_SZ * NTOK * CIN];    // [b][n][c]

// ============================================================================
// Kernel 1: 1x1-conv projections  Q = p^T Wq + bq,  K = b^T Wk + bk
// grid (NTOK/32, B, 2), block 256.  Tile: 32 n x 128 d, c chunked by 64.
// ============================================================================
__global__ __launch_bounds__(256) void proj_kernel(
    const float* __restrict__ p, const float* __restrict__ bin,
    const float* __restrict__ Wq, const float* __restrict__ bq,
    const float* __restrict__ Wk, const float* __restrict__ bk)
{
    __shared__ float wst[64][129];   // wst[cc][d] = W[d][c0+cc]
    __shared__ float xs [64][36];    // xs[cc][n]  = X[c0+cc][n0+n]

    const int nt = blockIdx.x, bb = blockIdx.y, z = blockIdx.z;
    const float* X    = (z == 0) ? p  : bin;
    const float* W    = (z == 0) ? Wq : Wk;
    const float* bias = (z == 0) ? bq : bk;
    float*       Out  = (z == 0) ? g_Q : g_K;

    const int t   = threadIdx.x;
    const int d   = t & 127;        // output channel
    const int ng  = t >> 7;         // 0..1 -> n sub-block
    const int n0  = ng * 16;
    const int gn0 = nt * 32;

    float acc[16];
    const float bv = bias[d];
#pragma unroll
    for (int j = 0; j < 16; j++) acc[j] = bv;

    const float* Xb = X + (size_t)bb * CIN * NTOK;

    for (int c0 = 0; c0 < CIN; c0 += 64) {
        for (int e = t; e < 64 * 128; e += 256) {       // W chunk (coalesced read)
            int cc = e & 63, dd = e >> 6;
            wst[cc][dd] = W[dd * CIN + c0 + cc];
        }
        for (int e = t; e < 64 * 32; e += 256) {        // x chunk (coalesced read)
            int cc = e >> 5, nn = e & 31;
            xs[cc][nn] = Xb[(size_t)(c0 + cc) * NTOK + gn0 + nn];
        }
        __syncthreads();
#pragma unroll 8
        for (int cc = 0; cc < 64; cc++) {
            const float w = wst[cc][d];
            const float4* xr = (const float4*)&xs[cc][n0];
#pragma unroll
            for (int j4 = 0; j4 < 4; j4++) {
                float4 xv = xr[j4];
                acc[j4 * 4 + 0] += w * xv.x;
                acc[j4 * 4 + 1] += w * xv.y;
                acc[j4 * 4 + 2] += w * xv.z;
                acc[j4 * 4 + 3] += w * xv.w;
            }
        }
        __syncthreads();
    }

    float* Ob = Out + (size_t)bb * NTOK * COUT;
#pragma unroll
    for (int j = 0; j < 16; j++)                        // coalesced: lanes -> consecutive d
        Ob[(size_t)(gn0 + n0 + j) * COUT + d] = acc[j];
}

// ============================================================================
// Kernel 2: V transpose  g_Vt[b][n][c] = bin[b][c][n]
// grid (NTOK/32, CIN/32, B), block (32, 8)
// ============================================================================
__global__ __launch_bounds__(256) void transpose_v_kernel(const float* __restrict__ bin)
{
    __shared__ float tile[32][33];
    const int bb = blockIdx.z;
    const int c0 = blockIdx.y * 32;
    const int n0 = blockIdx.x * 32;
    const int tx = threadIdx.x, ty = threadIdx.y;

    const float* src = bin + (size_t)bb * CIN * NTOK;
#pragma unroll
    for (int k = 0; k < 4; k++)
        tile[ty + 8 * k][tx] = src[(size_t)(c0 + ty + 8 * k) * NTOK + n0 + tx];
    __syncthreads();
    float* dst = g_Vt + (size_t)bb * NTOK * CIN;
#pragma unroll
    for (int k = 0; k < 4; k++)
        dst[(size_t)(n0 + ty + 8 * k) * CIN + c0 + tx] = tile[tx][ty + 8 * k];
}

// ============================================================================
// Kernel 3: flash attention, fp32.
// grid (NTOK/64, B), block 256, dynamic smem 93440 B, 2 CTAs/SM.
// Each CTA: 64 queries; loop over key blocks of 32.
// Thread (ty=t/16, tx=t%16) owns q = 4*ty..+3 and c = 4*tx + {0,64,128,192}+0..3
// ============================================================================
#define QS_ROW 132
#define KS_ROW 132
#define VS_ROW 260
#define SS_ROW 68
#define ATTN_SMEM_FLOATS (64*QS_ROW + 32*KS_ROW + 32*VS_ROW + 32*SS_ROW + 192)

__global__ __launch_bounds__(256, 2) void attn_kernel()
{
    extern __shared__ float smf[];
    float* Qs     = smf;                    // [64][132]
    float* Ks     = Qs + 64 * QS_ROW;       // [32][132]
    float* Vs     = Ks + 32 * KS_ROW;       // [32][260]
    float* Ss     = Vs + 32 * VS_ROW;       // [32][68]  scores, k-major
    float* rmax   = Ss + 32 * SS_ROW;       // [64]
    float* rsum   = rmax + 64;              // [64]
    float* ralpha = rsum + 64;              // [64]

    const int t  = threadIdx.x;
    const int bb = blockIdx.y;
    const int n0 = blockIdx.x * 64;

    const float* Qg = g_Q  + ((size_t)bb * NTOK + n0) * COUT;
    const float* Kg = g_K  + (size_t)bb * NTOK * COUT;
    const float* Vg = g_Vt + (size_t)bb * NTOK * CIN;

    { // load Q tile (64 x 128), float4, coalesced
        const float4* Qg4 = (const float4*)Qg;
        for (int e = t; e < 64 * 32; e += 256) {
            int qq = e >> 5, dd4 = e & 31;
            *(float4*)&Qs[qq * QS_ROW + dd4 * 4] = Qg4[qq * 32 + dd4];
        }
    }
    if (t < 64) { rmax[t] = -CUDART_INF_F; rsum[t] = 0.f; }

    const int ty = t >> 4, tx = t & 15;
    const int q0 = ty * 4;
    const int sq = t >> 2, ssub = t & 3;    // softmax mapping: 4 threads per q row

    float o[4][16];
#pragma unroll
    for (int i = 0; i < 4; i++)
#pragma unroll
        for (int j = 0; j < 16; j++) o[i][j] = 0.f;

    for (int kb = 0; kb < NTOK / 32; kb++) {
        const int m0 = kb * 32;
        __syncthreads();                    // previous stage-3 done before overwrite

        { // load K tile (32x128) and V tile (32x256)
            const float4* Kg4 = (const float4*)(Kg + (size_t)m0 * COUT);
            for (int e = t; e < 32 * 32; e += 256) {
                int mm = e >> 5, dd4 = e & 31;
                *(float4*)&Ks[mm * KS_ROW + dd4 * 4] = Kg4[mm * 32 + dd4];
            }
            const float4* Vg4 = (const float4*)(Vg + (size_t)m0 * CIN);
            for (int e = t; e < 32 * 64; e += 256) {
                int mm = e >> 6, cc4 = e & 63;
                *(float4*)&Vs[mm * VS_ROW + cc4 * 4] = Vg4[mm * 64 + cc4];
            }
        }
        __syncthreads();

        // ---- stage 1: scores S[k][q], k in {tx, tx+16}, q in q0..q0+3 ----
        {
            float s[4][2];
#pragma unroll
            for (int i = 0; i < 4; i++) { s[i][0] = 0.f; s[i][1] = 0.f; }
#pragma unroll 4
            for (int dd = 0; dd < 128; dd += 4) {
                float4 kv0 = *(const float4*)&Ks[tx * KS_ROW + dd];
                float4 kv1 = *(const float4*)&Ks[(tx + 16) * KS_ROW + dd];
#pragma unroll
                for (int i = 0; i < 4; i++) {
                    float4 qv = *(const float4*)&Qs[(q0 + i) * QS_ROW + dd];
                    s[i][0] += qv.x * kv0.x + qv.y * kv0.y + qv.z * kv0.z + qv.w * kv0.w;
                    s[i][1] += qv.x * kv1.x + qv.y * kv1.y + qv.z * kv1.z + qv.w * kv1.w;
                }
            }
            float4 a0 = make_float4(s[0][0], s[1][0], s[2][0], s[3][0]);
            float4 a1 = make_float4(s[0][1], s[1][1], s[2][1], s[3][1]);
            *(float4*)&Ss[tx * SS_ROW + q0]        = a0;
            *(float4*)&Ss[(tx + 16) * SS_ROW + q0] = a1;
        }
        __syncthreads();

        // ---- stage 2: online softmax (4 threads per q row, 8 keys each) ----
        {
            float vals[8];
#pragma unroll
            for (int i = 0; i < 8; i++) vals[i] = Ss[(ssub * 8 + i) * SS_ROW + sq];
            float pm = vals[0];
#pragma unroll
            for (int i = 1; i < 8; i++) pm = fmaxf(pm, vals[i]);
            pm = fmaxf(pm, __shfl_xor_sync(0xffffffffu, pm, 1));
            pm = fmaxf(pm, __shfl_xor_sync(0xffffffffu, pm, 2));
            const float mold = rmax[sq];
            const float mnew = fmaxf(mold, pm);
            float psum = 0.f;
#pragma unroll
            for (int i = 0; i < 8; i++) {
                float e = __expf(vals[i] - mnew);
                Ss[(ssub * 8 + i) * SS_ROW + sq] = e;
                psum += e;
            }
            psum += __shfl_xor_sync(0xffffffffu, psum, 1);
            psum += __shfl_xor_sync(0xffffffffu, psum, 2);
            if (ssub == 0) {
                const float alpha = __expf(mold - mnew);   // exp(-inf)=0 on iter 0
                rsum[sq]   = rsum[sq] * alpha + psum;
                rmax[sq]   = mnew;
                ralpha[sq] = alpha;
            }
        }
        __syncthreads();

        // ---- stage 3: O = O*alpha + P @ V ----
        {
            float a0 = ralpha[q0], a1 = ralpha[q0 + 1], a2 = ralpha[q0 + 2], a3 = ralpha[q0 + 3];
#pragma unroll
            for (int j = 0; j < 16; j++) {
                o[0][j] *= a0; o[1][j] *= a1; o[2][j] *= a2; o[3][j] *= a3;
            }
#pragma unroll 2
            for (int mm = 0; mm < 32; mm++) {
                float4 pv = *(const float4*)&Ss[mm * SS_ROW + q0];
#pragma unroll
                for (int j4 = 0; j4 < 4; j4++) {
                    float4 vv = *(const float4*)&Vs[mm * VS_ROW + (tx << 2) + (j4 << 6)];
                    o[0][j4*4+0] += pv.x*vv.x; o[0][j4*4+1] += pv.x*vv.y;
                    o[0][j4*4+2] += pv.x*vv.z; o[0][j4*4+3] += pv.x*vv.w;
                    o[1][j4*4+0] += pv.y*vv.x; o[1][j4*4+1] += pv.y*vv.y;
                    o[1][j4*4+2] += pv.y*vv.z; o[1][j4*4+3] += pv.y*vv.w;
                    o[2][j4*4+0] += pv.z*vv.x; o[2][j4*4+1] += pv.z*vv.y;
                    o[2][j4*4+2] += pv.z*vv.z; o[2][j4*4+3] += pv.z*vv.w;
                    o[3][j4*4+0] += pv.w*vv.x; o[3][j4*4+1] += pv.w*vv.y;
                    o[3][j4*4+2] += pv.w*vv.z; o[3][j4*4+3] += pv.w*vv.w;
                }
            }
        }
    }
    __syncthreads();

    // epilogue: divide by row sum, write Ot[b][n][c] (coalesced float4)
    float inv[4];
#pragma unroll
    for (int i = 0; i < 4; i++) inv[i] = 1.0f / rsum[q0 + i];
    float* Og = g_Ot + ((size_t)bb * NTOK + n0) * CIN;
#pragma unroll
    for (int i = 0; i < 4; i++) {
#pragma unroll
        for (int j4 = 0; j4 < 4; j4++) {
            float4 w = make_float4(o[i][j4*4+0] * inv[i], o[i][j4*4+1] * inv[i],
                                   o[i][j4*4+2] * inv[i], o[i][j4*4+3] * inv[i]);
            *(float4*)&Og[(size_t)(q0 + i) * CIN + (tx << 2) + (j4 << 6)] = w;
        }
    }
}

// ============================================================================
// Kernel 4: O transpose  out[b][c][n] = g_Ot[b][n][c]
// grid (NTOK/32, CIN/32, B), block (32, 8)
// ============================================================================
__global__ __launch_bounds__(256) void transpose_o_kernel(float* __restrict__ out)
{
    __shared__ float tile[32][33];
    const int bb = blockIdx.z;
    const int c0 = blockIdx.y * 32;
    const int n0 = blockIdx.x * 32;
    const int tx = threadIdx.x, ty = threadIdx.y;

    const float* src = g_Ot + (size_t)bb * NTOK * CIN;
#pragma unroll
    for (int k = 0; k < 4; k++)
        tile[ty + 8 * k][tx] = src[(size_t)(n0 + ty + 8 * k) * CIN + c0 + tx];
    __syncthreads();
    float* dst = out + (size_t)bb * CIN * NTOK;
#pragma unroll
    for (int k = 0; k < 4; k++)
        dst[(size_t)(c0 + ty + 8 * k) * NTOK + n0 + tx] = tile[tx][ty + 8 * k];
}

// ============================================================================
extern "C" void kernel_launch(void* const* d_in, const int* in_sizes, int n_in,
                              void* d_out, int out_size)
{
    const float* p   = (const float*)d_in[0];
    const float* bin = (const float*)d_in[1];
    const float* Wq  = (const float*)d_in[2];
    const float* bq  = (const float*)d_in[3];
    const float* Wk  = (const float*)d_in[4];
    const float* bk  = (const float*)d_in[5];
    float* out = (float*)d_out;

    cudaFuncSetAttribute(attn_kernel, cudaFuncAttributeMaxDynamicSharedMemorySize,
                         (int)(ATTN_SMEM_FLOATS * sizeof(float)));

    proj_kernel       <<<dim3(NTOK / 32, B_SZ, 2), 256>>>(p, bin, Wq, bq, Wk, bk);
    transpose_v_kernel<<<dim3(NTOK / 32, CIN / 32, B_SZ), dim3(32, 8)>>>(bin);
    attn_kernel       <<<dim3(NTOK / 64, B_SZ), 256,
                         ATTN_SMEM_FLOATS * sizeof(float)>>>();
    transpose_o_kernel<<<dim3(NTOK / 32, CIN / 32, B_SZ), dim3(32, 8)>>>(out);
}

// round 9
// speedup vs baseline: 2.1099x; 2.1030x over previous
#include <cuda_runtime.h>
#include <cuda_bf16.h>
#include <cstdint>

#define B_SZ 8
#define CIN  256
#define COUT 128
#define NTOK 4096
#define BM   64     // queries per CTA
#define BN   64     // keys per iteration

// ---------------------------------------------------------------------------
// Scratch (static device globals; no allocation)
// ---------------------------------------------------------------------------
__device__ __nv_bfloat16 g_Qh[B_SZ * NTOK * COUT];   // [b][n][d] hi
__device__ __nv_bfloat16 g_Ql[B_SZ * NTOK * COUT];   // [b][n][d] lo
__device__ __nv_bfloat16 g_Kh[B_SZ * NTOK * COUT];   // [b][m][d] hi
__device__ __nv_bfloat16 g_Kl[B_SZ * NTOK * COUT];   // [b][m][d] lo
__device__ __nv_bfloat16 g_Vh[B_SZ * CIN * NTOK];    // [b][c][m] hi (native layout)
__device__ __nv_bfloat16 g_Vl[B_SZ * CIN * NTOK];    // [b][c][m] lo

// ---------------------------------------------------------------------------
// Warp-MMA primitives (baseline PTX ISA -> compiles for compute_103)
// ---------------------------------------------------------------------------
__device__ __forceinline__ uint32_t smem_u32(const void* p) {
    uint32_t a;
    asm("{ .reg .u64 t; cvta.to.shared.u64 t, %1; cvt.u32.u64 %0, t; }"
        : "=r"(a) : "l"(p));
    return a;
}

__device__ __forceinline__ void ldsm4(uint32_t* r, uint32_t addr) {
    asm volatile("ldmatrix.sync.aligned.m8n8.x4.shared.b16 {%0,%1,%2,%3}, [%4];"
                 : "=r"(r[0]), "=r"(r[1]), "=r"(r[2]), "=r"(r[3]) : "r"(addr));
}

// D += A * B^T   (m16n8k16, bf16 in, fp32 acc)
__device__ __forceinline__ void mma16816(float* d, const uint32_t* a, const uint32_t* b) {
    asm volatile(
        "mma.sync.aligned.m16n8k16.row.col.f32.bf16.bf16.f32 "
        "{%0,%1,%2,%3}, {%4,%5,%6,%7}, {%8,%9}, {%0,%1,%2,%3};"
        : "+f"(d[0]), "+f"(d[1]), "+f"(d[2]), "+f"(d[3])
        : "r"(a[0]), "r"(a[1]), "r"(a[2]), "r"(a[3]), "r"(b[0]), "r"(b[1]));
}

// pack (lo-half = e0, hi-half = e1) as bf16x2
__device__ __forceinline__ uint32_t pack_bf16x2(float e0, float e1) {
    uint32_t u;
    asm("cvt.rn.bf16x2.f32 %0, %1, %2;" : "=r"(u) : "f"(e1), "f"(e0));
    return u;
}

// fast exp on the FMA pipe (no MUFU): exp(x) = 2^(x*log2e), poly deg-6, ~1e-7 rel
__device__ __forceinline__ float fexp(float s) {
    float y  = s * 1.4426950408889634f;
    float t  = y + 12582912.0f;            // round-to-nearest int in mantissa
    float nf = t - 12582912.0f;
    float f  = y - nf;                     // f in [-0.5, 0.5]
    int   ni = __float_as_int(t) - 0x4B400000;
    float p  = 1.5403530e-4f;
    p = fmaf(p, f, 1.3333558e-3f);
    p = fmaf(p, f, 9.6181291e-3f);
    p = fmaf(p, f, 5.5504109e-2f);
    p = fmaf(p, f, 2.4022651e-1f);
    p = fmaf(p, f, 6.9314718e-1f);
    p = fmaf(p, f, 1.0f);
    return p * __int_as_float((ni + 127) << 23);
}

// ---------------------------------------------------------------------------
// Kernel 1: projections, fp32 compute -> bf16 hi/lo split outputs
// ---------------------------------------------------------------------------
__global__ __launch_bounds__(256) void proj_kernel(
    const float* __restrict__ p, const float* __restrict__ bin,
    const float* __restrict__ Wq, const float* __restrict__ bq,
    const float* __restrict__ Wk, const float* __restrict__ bk)
{
    __shared__ float wst[64][129];
    __shared__ float xs [64][36];

    const int nt = blockIdx.x, bb = blockIdx.y, z = blockIdx.z;
    const float* X    = (z == 0) ? p  : bin;
    const float* W    = (z == 0) ? Wq : Wk;
    const float* bias = (z == 0) ? bq : bk;
    __nv_bfloat16* Oh = (z == 0) ? g_Qh : g_Kh;
    __nv_bfloat16* Ol = (z == 0) ? g_Ql : g_Kl;

    const int t  = threadIdx.x;
    const int d  = t & 127;
    const int n0 = (t >> 7) * 16;
    const int gn0 = nt * 32;

    float acc[16];
    const float bv = bias[d];
#pragma unroll
    for (int j = 0; j < 16; j++) acc[j] = bv;

    const float* Xb = X + (size_t)bb * CIN * NTOK;

    for (int c0 = 0; c0 < CIN; c0 += 64) {
        for (int e = t; e < 64 * 128; e += 256) {
            int cc = e & 63, dd = e >> 6;
            wst[cc][dd] = W[dd * CIN + c0 + cc];
        }
        for (int e = t; e < 64 * 32; e += 256) {
            int cc = e >> 5, nn = e & 31;
            xs[cc][nn] = Xb[(size_t)(c0 + cc) * NTOK + gn0 + nn];
        }
        __syncthreads();
#pragma unroll 8
        for (int cc = 0; cc < 64; cc++) {
            const float w = wst[cc][d];
            const float4* xr = (const float4*)&xs[cc][n0];
#pragma unroll
            for (int j4 = 0; j4 < 4; j4++) {
                float4 xv = xr[j4];
                acc[j4 * 4 + 0] += w * xv.x;
                acc[j4 * 4 + 1] += w * xv.y;
                acc[j4 * 4 + 2] += w * xv.z;
                acc[j4 * 4 + 3] += w * xv.w;
            }
        }
        __syncthreads();
    }

    const size_t ob = (size_t)bb * NTOK * COUT;
#pragma unroll
    for (int j = 0; j < 16; j++) {
        float v = acc[j];
        __nv_bfloat16 h = __float2bfloat16(v);
        __nv_bfloat16 l = __float2bfloat16(v - __bfloat162float(h));
        size_t idx = ob + (size_t)(gn0 + n0 + j) * COUT + d;
        Oh[idx] = h;
        Ol[idx] = l;
    }
}

// ---------------------------------------------------------------------------
// Kernel 2: V hi/lo split (keeps native [b][c][m] layout)
// ---------------------------------------------------------------------------
__global__ __launch_bounds__(256) void vconv_kernel(const float* __restrict__ bin)
{
    size_t i = ((size_t)blockIdx.x * 256 + threadIdx.x) * 4;
    float4 v = *(const float4*)(bin + i);
    __nv_bfloat16 hx = __float2bfloat16(v.x);
    __nv_bfloat16 hy = __float2bfloat16(v.y);
    __nv_bfloat16 hz = __float2bfloat16(v.z);
    __nv_bfloat16 hw = __float2bfloat16(v.w);
    __nv_bfloat16 lx = __float2bfloat16(v.x - __bfloat162float(hx));
    __nv_bfloat16 ly = __float2bfloat16(v.y - __bfloat162float(hy));
    __nv_bfloat16 lz = __float2bfloat16(v.z - __bfloat162float(hz));
    __nv_bfloat16 lw = __float2bfloat16(v.w - __bfloat162float(hw));
    __nv_bfloat162* Vh2 = (__nv_bfloat162*)(g_Vh + i);
    __nv_bfloat162* Vl2 = (__nv_bfloat162*)(g_Vl + i);
    Vh2[0] = __halves2bfloat162(hx, hy);
    Vh2[1] = __halves2bfloat162(hz, hw);
    Vl2[0] = __halves2bfloat162(lx, ly);
    Vl2[1] = __halves2bfloat162(lz, lw);
}

// ---------------------------------------------------------------------------
// Kernel 3: warp-MMA flash attention, split-bf16 (3-MMA) QK^T and PV.
// grid (64, 8), block 256 (8 warps), dyn smem 127488 B, 1 CTA/SM.
// No online max: O accumulates in registers across all 64 key blocks.
// smem rows padded to 272B/144B -> ldmatrix bank-conflict-free (4-bank shift).
// ---------------------------------------------------------------------------
#define SM_KH  0
#define SM_KL  17408
#define SM_VH  34816
#define SM_VL  71680
#define SM_PH  108544
#define SM_PL  117760
#define SM_LS  126976
#define ATTN_SMEM 127488
// Q staging (prologue only) borrows the V region:
#define SM_QH  SM_VH
#define SM_QL  (SM_VH + 17408)
// O staging (epilogue only) borrows the V region: 256 rows x 272B

__global__ __launch_bounds__(256, 1) void attn_mma_kernel(float* __restrict__ out)
{
    extern __shared__ char sm[];
    const uint32_t smb = smem_u32(sm);

    const int t    = threadIdx.x;
    const int wid  = t >> 5, lane = t & 31;
    const int bb   = blockIdx.y;
    const int n0   = blockIdx.x * BM;

    // QK-stage roles
    const int qg = wid & 3;          // 16 q rows each
    const int kg = wid >> 2;         // 32 keys each
    // PV-stage roles
    const int qg2 = wid >> 2;        // 32 q rows each (2 m16 tiles)
    const int cg  = wid & 3;         // 64 value-channels each (8 n8 tiles)

    const int g  = lane >> 2, tq = lane & 3;
    const uint32_t rowp  = (lane & 7) + ((lane >> 4) << 3);   // B-frag row sel
    const uint32_t koff  = ((lane >> 3) & 1) * 16;            // B-frag k sel
    const uint32_t arow  = (lane & 15);                       // A-frag row sel
    const uint32_t akoff = (lane >> 4) * 16;                  // A-frag k sel

    // ---- prologue: stage Q to (borrowed) smem, load Q fragments to regs ----
    {
        const uint4* Qh4 = (const uint4*)(g_Qh + ((size_t)bb * NTOK + n0) * COUT);
        const uint4* Ql4 = (const uint4*)(g_Ql + ((size_t)bb * NTOK + n0) * COUT);
        for (int e = t; e < 64 * 16; e += 256) {
            int r = e >> 4, c = e & 15;
            *(uint4*)(sm + SM_QH + r * 272 + c * 16) = Qh4[e];
            *(uint4*)(sm + SM_QL + r * 272 + c * 16) = Ql4[e];
        }
    }
    __syncthreads();

    uint32_t qfh[8][4], qfl[8][4];
#pragma unroll
    for (int ks = 0; ks < 8; ks++) {
        uint32_t a = smb + (qg * 16 + arow) * 272 + ks * 32 + akoff;
        ldsm4(qfh[ks], a + SM_QH);
        ldsm4(qfl[ks], a + SM_QL);
    }

    float of[2][8][4];
#pragma unroll
    for (int mt = 0; mt < 2; mt++)
#pragma unroll
        for (int nt = 0; nt < 8; nt++)
#pragma unroll
            for (int j = 0; j < 4; j++) of[mt][nt][j] = 0.f;

    float Lacc0 = 0.f, Lacc1 = 0.f;

    const __nv_bfloat16* Khg = g_Kh + (size_t)bb * NTOK * COUT;
    const __nv_bfloat16* Klg = g_Kl + (size_t)bb * NTOK * COUT;

    for (int kb = 0; kb < NTOK / BN; kb++) {
        const int m0 = kb * BN;
        __syncthreads();   // prev PV (V,P reads) + prologue ldmatrix done

        // ---- load K (64x128 hi/lo) and V (256x64 hi/lo) into padded smem ----
        {
            const uint4* Kh4 = (const uint4*)(Khg + (size_t)m0 * COUT);
            const uint4* Kl4 = (const uint4*)(Klg + (size_t)m0 * COUT);
            for (int e = t; e < 64 * 16; e += 256) {
                int r = e >> 4, c = e & 15;
                *(uint4*)(sm + SM_KH + r * 272 + c * 16) = Kh4[e];
                *(uint4*)(sm + SM_KL + r * 272 + c * 16) = Kl4[e];
            }
            for (int e = t; e < 256 * 8; e += 256) {
                int r = e >> 3, c8 = e & 7;
                size_t gi = ((size_t)bb * CIN + r) * NTOK + m0 + c8 * 8;
                *(uint4*)(sm + SM_VH + r * 144 + c8 * 16) = *(const uint4*)(g_Vh + gi);
                *(uint4*)(sm + SM_VL + r * 144 + c8 * 16) = *(const uint4*)(g_Vl + gi);
            }
        }
        __syncthreads();

        // ---- QK: S[16q x 32k] = Qh*Kh + Qh*Kl + Ql*Kh (fp32 acc) ----
        float sf[4][4];
#pragma unroll
        for (int nt = 0; nt < 4; nt++)
#pragma unroll
            for (int j = 0; j < 4; j++) sf[nt][j] = 0.f;

#pragma unroll
        for (int ks = 0; ks < 8; ks++) {
            uint32_t b0h[4], b1h[4], b0l[4], b1l[4];
            uint32_t a0 = smb + (kg * 32 + rowp) * 272 + ks * 32 + koff;
            uint32_t a1 = smb + (kg * 32 + 16 + rowp) * 272 + ks * 32 + koff;
            ldsm4(b0h, a0 + SM_KH); ldsm4(b1h, a1 + SM_KH);
            ldsm4(b0l, a0 + SM_KL); ldsm4(b1l, a1 + SM_KL);

            mma16816(sf[0], qfh[ks], b0h + 0); mma16816(sf[1], qfh[ks], b0h + 2);
            mma16816(sf[2], qfh[ks], b1h + 0); mma16816(sf[3], qfh[ks], b1h + 2);
            mma16816(sf[0], qfh[ks], b0l + 0); mma16816(sf[1], qfh[ks], b0l + 2);
            mma16816(sf[2], qfh[ks], b1l + 0); mma16816(sf[3], qfh[ks], b1l + 2);
            mma16816(sf[0], qfl[ks], b0h + 0); mma16816(sf[1], qfl[ks], b0h + 2);
            mma16816(sf[2], qfl[ks], b1h + 0); mma16816(sf[3], qfl[ks], b1h + 2);
        }

        // ---- exp (FMA-pipe poly), L accumulate, P -> smem bf16 hi/lo ----
        {
            const int r0 = qg * 16 + g, r1 = r0 + 8;
#pragma unroll
            for (int nt = 0; nt < 4; nt++) {
                float e00 = fexp(sf[nt][0]);
                float e01 = fexp(sf[nt][1]);
                float e10 = fexp(sf[nt][2]);
                float e11 = fexp(sf[nt][3]);
                Lacc0 += e00 + e01;
                Lacc1 += e10 + e11;
                const int cbyte = (kg * 32 + nt * 8 + 2 * tq) * 2;
                uint32_t h0 = pack_bf16x2(e00, e01);
                uint32_t h1 = pack_bf16x2(e10, e11);
                float l00 = e00 - __uint_as_float(h0 << 16);
                float l01 = e01 - __uint_as_float(h0 & 0xFFFF0000u);
                float l10 = e10 - __uint_as_float(h1 << 16);
                float l11 = e11 - __uint_as_float(h1 & 0xFFFF0000u);
                *(uint32_t*)(sm + SM_PH + r0 * 144 + cbyte) = h0;
                *(uint32_t*)(sm + SM_PH + r1 * 144 + cbyte) = h1;
                *(uint32_t*)(sm + SM_PL + r0 * 144 + cbyte) = pack_bf16x2(l00, l01);
                *(uint32_t*)(sm + SM_PL + r1 * 144 + cbyte) = pack_bf16x2(l10, l11);
            }
        }
        __syncthreads();

        // ---- PV: O[32q x 64c] += Ph*Vh + Ph*Vl + Pl*Vh ----
#pragma unroll
        for (int kk = 0; kk < 4; kk++) {
            uint32_t ah[2][4], al[2][4];
#pragma unroll
            for (int mt = 0; mt < 2; mt++) {
                uint32_t a = smb + (qg2 * 32 + mt * 16 + arow) * 144 + kk * 32 + akoff;
                ldsm4(ah[mt], a + SM_PH);
                ldsm4(al[mt], a + SM_PL);
            }
#pragma unroll
            for (int pp = 0; pp < 4; pp++) {
                uint32_t vh[4], vl[4];
                uint32_t a = smb + (cg * 64 + pp * 16 + rowp) * 144 + kk * 32 + koff;
                ldsm4(vh, a + SM_VH);
                ldsm4(vl, a + SM_VL);
#pragma unroll
                for (int mt = 0; mt < 2; mt++) {
                    mma16816(of[mt][2 * pp],     ah[mt], vh + 0);
                    mma16816(of[mt][2 * pp + 1], ah[mt], vh + 2);
                    mma16816(of[mt][2 * pp],     ah[mt], vl + 0);
                    mma16816(of[mt][2 * pp + 1], ah[mt], vl + 2);
                    mma16816(of[mt][2 * pp],     al[mt], vh + 0);
                    mma16816(of[mt][2 * pp + 1], al[mt], vh + 2);
                }
            }
        }
    }

    // ---- L reduction: quad shuffle, then per-(kg,row) unique smem write ----
    Lacc0 += __shfl_xor_sync(0xffffffffu, Lacc0, 1);
    Lacc0 += __shfl_xor_sync(0xffffffffu, Lacc0, 2);
    Lacc1 += __shfl_xor_sync(0xffffffffu, Lacc1, 1);
    Lacc1 += __shfl_xor_sync(0xffffffffu, Lacc1, 2);
    float* Ls = (float*)(sm + SM_LS);          // [2][64]
    if (tq == 0) {
        Ls[kg * 64 + qg * 16 + g]     = Lacc0;
        Ls[kg * 64 + qg * 16 + g + 8] = Lacc1;
    }
    __syncthreads();

    // ---- epilogue: normalize, stage O[c][n] in (borrowed) V smem ----
    {
        float* Osm = (float*)(sm + SM_VH);     // 256 rows x 68 floats (272B)
        const int r0 = qg2 * 32 + g;
#pragma unroll
        for (int mt = 0; mt < 2; mt++) {
            const int ra = r0 + mt * 16, rb = ra + 8;
            const float ia = 1.0f / (Ls[ra] + Ls[64 + ra]);
            const float ib = 1.0f / (Ls[rb] + Ls[64 + rb]);
#pragma unroll
            for (int nt = 0; nt < 8; nt++) {
                const int c0 = cg * 64 + nt * 8 + 2 * tq;
                Osm[(c0)     * 68 + ra] = of[mt][nt][0] * ia;
                Osm[(c0 + 1) * 68 + ra] = of[mt][nt][1] * ia;
                Osm[(c0)     * 68 + rb] = of[mt][nt][2] * ib;
                Osm[(c0 + 1) * 68 + rb] = of[mt][nt][3] * ib;
            }
        }
    }
    __syncthreads();

    // ---- coalesced store: out[b][c][n0..n0+63] ----
    {
        const float* Osm = (const float*)(sm + SM_VH);
        float* ob = out + (size_t)bb * CIN * NTOK + n0;
        for (int e = t; e < 256 * 16; e += 256) {
            int c = e >> 4, g4 = e & 15;
            *(float4*)(ob + (size_t)c * NTOK + g4 * 4) =
                *(const float4*)(Osm + c * 68 + g4 * 4);
        }
    }
}

// ---------------------------------------------------------------------------
extern "C" void kernel_launch(void* const* d_in, const int* in_sizes, int n_in,
                              void* d_out, int out_size)
{
    const float* p   = (const float*)d_in[0];
    const float* bin = (const float*)d_in[1];
    const float* Wq  = (const float*)d_in[2];
    const float* bq  = (const float*)d_in[3];
    const float* Wk  = (const float*)d_in[4];
    const float* bk  = (const float*)d_in[5];
    float* out = (float*)d_out;

    cudaFuncSetAttribute(attn_mma_kernel, cudaFuncAttributeMaxDynamicSharedMemorySize,
                         ATTN_SMEM);

    proj_kernel  <<<dim3(NTOK / 32, B_SZ, 2), 256>>>(p, bin, Wq, bq, Wk, bk);
    vconv_kernel <<<(B_SZ * CIN * NTOK) / (256 * 4), 256>>>(bin);
    attn_mma_kernel<<<dim3(NTOK / BM, B_SZ), 256, ATTN_SMEM>>>(out);
}

// round 12
// speedup vs baseline: 2.7821x; 1.3186x over previous
#include <cuda_runtime.h>
#include <cuda_bf16.h>
#include <cstdint>

#define B_SZ 8
#define CIN  256
#define COUT 128
#define NTOK 4096
#define BM   64     // queries per CTA
#define BN   64     // keys per iteration
#define NKB  (NTOK / BN)

// ---------------------------------------------------------------------------
// Scratch (static device globals; no allocation)
// ---------------------------------------------------------------------------
__device__ __nv_bfloat16 g_Qh[B_SZ * NTOK * COUT];   // [b][n][d] hi
__device__ __nv_bfloat16 g_Ql[B_SZ * NTOK * COUT];   // [b][n][d] lo
__device__ __nv_bfloat16 g_Kh[B_SZ * NTOK * COUT];   // [b][m][d] hi
__device__ __nv_bfloat16 g_Kl[B_SZ * NTOK * COUT];   // [b][m][d] lo
__device__ __nv_bfloat16 g_Vh[B_SZ * CIN * NTOK];    // [b][c][m] hi (native layout)
__device__ __nv_bfloat16 g_Vl[B_SZ * CIN * NTOK];    // [b][c][m] lo

// ---------------------------------------------------------------------------
// Warp-MMA / async-copy primitives (baseline PTX ISA -> ok for compute_103)
// ---------------------------------------------------------------------------
__device__ __forceinline__ uint32_t smem_u32(const void* p) {
    uint32_t a;
    asm("{ .reg .u64 t; cvta.to.shared.u64 t, %1; cvt.u32.u64 %0, t; }"
        : "=r"(a) : "l"(p));
    return a;
}

__device__ __forceinline__ void ldsm4(uint32_t* r, uint32_t addr) {
    asm volatile("ldmatrix.sync.aligned.m8n8.x4.shared.b16 {%0,%1,%2,%3}, [%4];"
                 : "=r"(r[0]), "=r"(r[1]), "=r"(r[2]), "=r"(r[3]) : "r"(addr));
}

// D += A * B^T   (m16n8k16, bf16 in, fp32 acc)
__device__ __forceinline__ void mma16816(float* d, const uint32_t* a, const uint32_t* b) {
    asm volatile(
        "mma.sync.aligned.m16n8k16.row.col.f32.bf16.bf16.f32 "
        "{%0,%1,%2,%3}, {%4,%5,%6,%7}, {%8,%9}, {%0,%1,%2,%3};"
        : "+f"(d[0]), "+f"(d[1]), "+f"(d[2]), "+f"(d[3])
        : "r"(a[0]), "r"(a[1]), "r"(a[2]), "r"(a[3]), "r"(b[0]), "r"(b[1]));
}

__device__ __forceinline__ uint32_t pack_bf16x2(float e0, float e1) {
    uint32_t u;
    asm("cvt.rn.bf16x2.f32 %0, %1, %2;" : "=r"(u) : "f"(e1), "f"(e0));
    return u;
}

__device__ __forceinline__ void cp16(uint32_t dst, const void* src) {
    asm volatile("cp.async.cg.shared.global [%0], [%1], 16;" :: "r"(dst), "l"(src));
}
#define CP_COMMIT() asm volatile("cp.async.commit_group;" ::: "memory")
#define CP_WAIT(n)  asm volatile("cp.async.wait_group %0;" :: "n"(n) : "memory")

// fast exp on the FMA pipe (no MUFU): exp(x) = 2^(x*log2e), poly deg-6, ~1e-7 rel
__device__ __forceinline__ float fexp(float s) {
    float y  = s * 1.4426950408889634f;
    float t  = y + 12582912.0f;
    float nf = t - 12582912.0f;
    float f  = y - nf;
    int   ni = __float_as_int(t) - 0x4B400000;
    float p  = 1.5403530e-4f;
    p = fmaf(p, f, 1.3333558e-3f);
    p = fmaf(p, f, 9.6181291e-3f);
    p = fmaf(p, f, 5.5504109e-2f);
    p = fmaf(p, f, 2.4022651e-1f);
    p = fmaf(p, f, 6.9314718e-1f);
    p = fmaf(p, f, 1.0f);
    return p * __int_as_float((ni + 127) << 23);
}

// ---------------------------------------------------------------------------
// Kernel 1: projections, fp32 compute -> bf16 hi/lo split outputs
// ---------------------------------------------------------------------------
__global__ __launch_bounds__(256) void proj_kernel(
    const float* __restrict__ p, const float* __restrict__ bin,
    const float* __restrict__ Wq, const float* __restrict__ bq,
    const float* __restrict__ Wk, const float* __restrict__ bk)
{
    __shared__ float wst[64][129];
    __shared__ float xs [64][36];

    const int nt = blockIdx.x, bb = blockIdx.y, z = blockIdx.z;
    const float* X    = (z == 0) ? p  : bin;
    const float* W    = (z == 0) ? Wq : Wk;
    const float* bias = (z == 0) ? bq : bk;
    __nv_bfloat16* Oh = (z == 0) ? g_Qh : g_Kh;
    __nv_bfloat16* Ol = (z == 0) ? g_Ql : g_Kl;

    const int t  = threadIdx.x;
    const int d  = t & 127;
    const int n0 = (t >> 7) * 16;
    const int gn0 = nt * 32;

    float acc[16];
    const float bv = bias[d];
#pragma unroll
    for (int j = 0; j < 16; j++) acc[j] = bv;

    const float* Xb = X + (size_t)bb * CIN * NTOK;

    for (int c0 = 0; c0 < CIN; c0 += 64) {
        for (int e = t; e < 64 * 128; e += 256) {
            int cc = e & 63, dd = e >> 6;
            wst[cc][dd] = W[dd * CIN + c0 + cc];
        }
        for (int e = t; e < 64 * 32; e += 256) {
            int cc = e >> 5, nn = e & 31;
            xs[cc][nn] = Xb[(size_t)(c0 + cc) * NTOK + gn0 + nn];
        }
        __syncthreads();
#pragma unroll 8
        for (int cc = 0; cc < 64; cc++) {
            const float w = wst[cc][d];
            const float4* xr = (const float4*)&xs[cc][n0];
#pragma unroll
            for (int j4 = 0; j4 < 4; j4++) {
                float4 xv = xr[j4];
                acc[j4 * 4 + 0] += w * xv.x;
                acc[j4 * 4 + 1] += w * xv.y;
                acc[j4 * 4 + 2] += w * xv.z;
                acc[j4 * 4 + 3] += w * xv.w;
            }
        }
        __syncthreads();
    }

    const size_t ob = (size_t)bb * NTOK * COUT;
#pragma unroll
    for (int j = 0; j < 16; j++) {
        float v = acc[j];
        __nv_bfloat16 h = __float2bfloat16(v);
        __nv_bfloat16 l = __float2bfloat16(v - __bfloat162float(h));
        size_t idx = ob + (size_t)(gn0 + n0 + j) * COUT + d;
        Oh[idx] = h;
        Ol[idx] = l;
    }
}

// ---------------------------------------------------------------------------
// Kernel 2: V hi/lo split (keeps native [b][c][m] layout)
// ---------------------------------------------------------------------------
__global__ __launch_bounds__(256) void vconv_kernel(const float* __restrict__ bin)
{
    size_t i = ((size_t)blockIdx.x * 256 + threadIdx.x) * 4;
    float4 v = *(const float4*)(bin + i);
    __nv_bfloat16 hx = __float2bfloat16(v.x);
    __nv_bfloat16 hy = __float2bfloat16(v.y);
    __nv_bfloat16 hz = __float2bfloat16(v.z);
    __nv_bfloat16 hw = __float2bfloat16(v.w);
    __nv_bfloat16 lx = __float2bfloat16(v.x - __bfloat162float(hx));
    __nv_bfloat16 ly = __float2bfloat16(v.y - __bfloat162float(hy));
    __nv_bfloat16 lz = __float2bfloat16(v.z - __bfloat162float(hz));
    __nv_bfloat16 lw = __float2bfloat16(v.w - __bfloat162float(hw));
    __nv_bfloat162* Vh2 = (__nv_bfloat162*)(g_Vh + i);
    __nv_bfloat162* Vl2 = (__nv_bfloat162*)(g_Vl + i);
    Vh2[0] = __halves2bfloat162(hx, hy);
    Vh2[1] = __halves2bfloat162(hz, hw);
    Vl2[0] = __halves2bfloat162(lx, ly);
    Vl2[1] = __halves2bfloat162(lz, lw);
}

// ---------------------------------------------------------------------------
// Kernel 3: warp-MMA flash attention, cp.async pipelined.
// K double-buffered (hidden); V single-buffered, issued early each iter
// (overlaps QK+exp). 2 syncthreads per iteration.
// ---------------------------------------------------------------------------
#define SM_K0   0                    // K buf0: hi 17408 + lo 17408
#define SM_K1   34816                // K buf1
#define SM_VH   69632                // V hi: 256 rows x 144B
#define SM_VL   106496               // V lo
#define SM_PH   143360               // P hi: 64 rows x 144B
#define SM_PL   152576               // P lo
#define SM_LS   161792               // L[2][64]
#define ATTN_SMEM 162304
// prologue Q staging / epilogue O staging borrow the V region:
#define SM_QH   SM_VH
#define SM_QL   (SM_VH + 17408)
#define SM_OS   SM_VH                // 256 rows x 272B = 69632 <= 73728

__global__ __launch_bounds__(256, 1) void attn_mma_kernel(float* __restrict__ out)
{
    extern __shared__ char sm[];
    const uint32_t smb = smem_u32(sm);

    const int t    = threadIdx.x;
    const int wid  = t >> 5, lane = t & 31;
    const int bb   = blockIdx.y;
    const int n0   = blockIdx.x * BM;

    const int qg = wid & 3;          // QK: 16 q rows each
    const int kg = wid >> 2;         // QK: 32 keys each
    const int qg2 = wid >> 2;        // PV: 32 q rows each
    const int cg  = wid & 3;         // PV: 64 value-channels each

    const int g  = lane >> 2, tq = lane & 3;
    const uint32_t rowp  = (lane & 7) + ((lane >> 4) << 3);
    const uint32_t koff  = ((lane >> 3) & 1) * 16;
    const uint32_t arow  = (lane & 15);
    const uint32_t akoff = (lane >> 4) * 16;

    const __nv_bfloat16* Khg = g_Kh + (size_t)bb * NTOK * COUT;
    const __nv_bfloat16* Klg = g_Kl + (size_t)bb * NTOK * COUT;

    // ---- issue K[0] immediately (overlaps Q staging) ----
    {
        const uint32_t kb0 = smb + SM_K0;
        for (int e = t; e < 64 * 16; e += 256) {
            int r = e >> 4, c = e & 15;
            uint32_t d = kb0 + r * 272 + c * 16;
            cp16(d,         Khg + e * 8);
            cp16(d + 17408, Klg + e * 8);
        }
    }
    CP_COMMIT();

    // ---- stage Q to (borrowed) V region, load Q fragments to regs ----
    {
        const uint4* Qh4 = (const uint4*)(g_Qh + ((size_t)bb * NTOK + n0) * COUT);
        const uint4* Ql4 = (const uint4*)(g_Ql + ((size_t)bb * NTOK + n0) * COUT);
        for (int e = t; e < 64 * 16; e += 256) {
            int r = e >> 4, c = e & 15;
            *(uint4*)(sm + SM_QH + r * 272 + c * 16) = Qh4[e];
            *(uint4*)(sm + SM_QL + r * 272 + c * 16) = Ql4[e];
        }
    }
    __syncthreads();

    uint32_t qfh[8][4], qfl[8][4];
#pragma unroll
    for (int ks = 0; ks < 8; ks++) {
        uint32_t a = smb + (qg * 16 + arow) * 272 + ks * 32 + akoff;
        ldsm4(qfh[ks], a + SM_QH);
        ldsm4(qfl[ks], a + SM_QL);
    }

    float of[2][8][4];
#pragma unroll
    for (int mt = 0; mt < 2; mt++)
#pragma unroll
        for (int nt = 0; nt < 8; nt++)
#pragma unroll
            for (int j = 0; j < 4; j++) of[mt][nt][j] = 0.f;

    float Lacc0 = 0.f, Lacc1 = 0.f;

    for (int kb = 0; kb < NKB; kb++) {
        const int m0 = kb * BN;
        const uint32_t kcur = smb + ((kb & 1) ? SM_K1 : SM_K0);

        CP_WAIT(0);          // K[kb] arrived (this thread)
        __syncthreads();     // K[kb] visible to all; prev PV done; Q-ldsm done (kb=0)

        // ---- issue V[kb] (consumed in PV phase; flight overlaps QK+exp) ----
        for (int e = t; e < 256 * 8; e += 256) {
            int r = e >> 3, c8 = e & 7;
            size_t gi = ((size_t)bb * CIN + r) * NTOK + m0 + c8 * 8;
            uint32_t d = smb + SM_VH + r * 144 + c8 * 16;
            cp16(d,                     g_Vh + gi);
            cp16(d + (SM_VL - SM_VH),   g_Vl + gi);
        }
        CP_COMMIT();

        // ---- issue K[kb+1] into the other buffer (empty commit on last) ----
        if (kb + 1 < NKB) {
            const uint32_t knxt = smb + (((kb + 1) & 1) ? SM_K1 : SM_K0);
            const __nv_bfloat16* kh = Khg + (size_t)(m0 + BN) * COUT;
            const __nv_bfloat16* kl = Klg + (size_t)(m0 + BN) * COUT;
            for (int e = t; e < 64 * 16; e += 256) {
                int r = e >> 4, c = e & 15;
                uint32_t d = knxt + r * 272 + c * 16;
                cp16(d,         kh + e * 8);
                cp16(d + 17408, kl + e * 8);
            }
        }
        CP_COMMIT();

        // ---- QK: S[16q x 32k] = Qh*Kh + Qh*Kl + Ql*Kh (fp32 acc) ----
        float sf[4][4];
#pragma unroll
        for (int nt = 0; nt < 4; nt++)
#pragma unroll
            for (int j = 0; j < 4; j++) sf[nt][j] = 0.f;

#pragma unroll
        for (int ks = 0; ks < 8; ks++) {
            uint32_t b0h[4], b1h[4], b0l[4], b1l[4];
            uint32_t a0 = kcur + (kg * 32 + rowp) * 272 + ks * 32 + koff;
            uint32_t a1 = kcur + (kg * 32 + 16 + rowp) * 272 + ks * 32 + koff;
            ldsm4(b0h, a0);          ldsm4(b1h, a1);
            ldsm4(b0l, a0 + 17408);  ldsm4(b1l, a1 + 17408);

            mma16816(sf[0], qfh[ks], b0h + 0); mma16816(sf[1], qfh[ks], b0h + 2);
            mma16816(sf[2], qfh[ks], b1h + 0); mma16816(sf[3], qfh[ks], b1h + 2);
            mma16816(sf[0], qfh[ks], b0l + 0); mma16816(sf[1], qfh[ks], b0l + 2);
            mma16816(sf[2], qfh[ks], b1l + 0); mma16816(sf[3], qfh[ks], b1l + 2);
            mma16816(sf[0], qfl[ks], b0h + 0); mma16816(sf[1], qfl[ks], b0h + 2);
            mma16816(sf[2], qfl[ks], b1h + 0); mma16816(sf[3], qfl[ks], b1h + 2);
        }

        // ---- exp (FMA-pipe poly), L accumulate, P -> smem bf16 hi/lo ----
        {
            const int r0 = qg * 16 + g, r1 = r0 + 8;
#pragma unroll
            for (int nt = 0; nt < 4; nt++) {
                float e00 = fexp(sf[nt][0]);
                float e01 = fexp(sf[nt][1]);
                float e10 = fexp(sf[nt][2]);
                float e11 = fexp(sf[nt][3]);
                Lacc0 += e00 + e01;
                Lacc1 += e10 + e11;
                const int cbyte = (kg * 32 + nt * 8 + 2 * tq) * 2;
                uint32_t h0 = pack_bf16x2(e00, e01);
                uint32_t h1 = pack_bf16x2(e10, e11);
                float l00 = e00 - __uint_as_float(h0 << 16);
                float l01 = e01 - __uint_as_float(h0 & 0xFFFF0000u);
                float l10 = e10 - __uint_as_float(h1 << 16);
                float l11 = e11 - __uint_as_float(h1 & 0xFFFF0000u);
                *(uint32_t*)(sm + SM_PH + r0 * 144 + cbyte) = h0;
                *(uint32_t*)(sm + SM_PH + r1 * 144 + cbyte) = h1;
                *(uint32_t*)(sm + SM_PL + r0 * 144 + cbyte) = pack_bf16x2(l00, l01);
                *(uint32_t*)(sm + SM_PL + r1 * 144 + cbyte) = pack_bf16x2(l10, l11);
            }
        }

        CP_WAIT(1);          // V[kb] arrived (K[kb+1] may still be in flight)
        __syncthreads();     // V + P visible to all

        // ---- PV: O[32q x 64c] += Ph*Vh + Ph*Vl + Pl*Vh ----
#pragma unroll
        for (int kk = 0; kk < 4; kk++) {
            uint32_t ah[2][4], al[2][4];
#pragma unroll
            for (int mt = 0; mt < 2; mt++) {
                uint32_t a = smb + (qg2 * 32 + mt * 16 + arow) * 144 + kk * 32 + akoff;
                ldsm4(ah[mt], a + SM_PH);
                ldsm4(al[mt], a + SM_PL);
            }
#pragma unroll
            for (int pp = 0; pp < 4; pp++) {
                uint32_t vh[4], vl[4];
                uint32_t a = smb + (cg * 64 + pp * 16 + rowp) * 144 + kk * 32 + koff;
                ldsm4(vh, a + SM_VH);
                ldsm4(vl, a + SM_VL);
#pragma unroll
                for (int mt = 0; mt < 2; mt++) {
                    mma16816(of[mt][2 * pp],     ah[mt], vh + 0);
                    mma16816(of[mt][2 * pp + 1], ah[mt], vh + 2);
                    mma16816(of[mt][2 * pp],     ah[mt], vl + 0);
                    mma16816(of[mt][2 * pp + 1], ah[mt], vl + 2);
                    mma16816(of[mt][2 * pp],     al[mt], vh + 0);
                    mma16816(of[mt][2 * pp + 1], al[mt], vh + 2);
                }
            }
        }
    }

    // ---- L reduction ----
    Lacc0 += __shfl_xor_sync(0xffffffffu, Lacc0, 1);
    Lacc0 += __shfl_xor_sync(0xffffffffu, Lacc0, 2);
    Lacc1 += __shfl_xor_sync(0xffffffffu, Lacc1, 1);
    Lacc1 += __shfl_xor_sync(0xffffffffu, Lacc1, 2);
    float* Ls = (float*)(sm + SM_LS);          // [2][64]
    if (tq == 0) {
        Ls[kg * 64 + qg * 16 + g]     = Lacc0;
        Ls[kg * 64 + qg * 16 + g + 8] = Lacc1;
    }
    __syncthreads();

    // ---- epilogue: normalize, stage O[c][n] in (borrowed) V smem ----
    {
        float* Osm = (float*)(sm + SM_OS);     // 256 rows x 68 floats
        const int r0 = qg2 * 32 + g;
#pragma unroll
        for (int mt = 0; mt < 2; mt++) {
            const int ra = r0 + mt * 16, rb = ra + 8;
            const float ia = 1.0f / (Ls[ra] + Ls[64 + ra]);
            const float ib = 1.0f / (Ls[rb] + Ls[64 + rb]);
#pragma unroll
            for (int nt = 0; nt < 8; nt++) {
                const int c0 = cg * 64 + nt * 8 + 2 * tq;
                Osm[(c0)     * 68 + ra] = of[mt][nt][0] * ia;
                Osm[(c0 + 1) * 68 + ra] = of[mt][nt][1] * ia;
                Osm[(c0)     * 68 + rb] = of[mt][nt][2] * ib;
                Osm[(c0 + 1) * 68 + rb] = of[mt][nt][3] * ib;
            }
        }
    }
    __syncthreads();

    // ---- coalesced store: out[b][c][n0..n0+63] ----
    {
        const float* Osm = (const float*)(sm + SM_OS);
        float* ob = out + (size_t)bb * CIN * NTOK + n0;
        for (int e = t; e < 256 * 16; e += 256) {
            int c = e >> 4, g4 = e & 15;
            *(float4*)(ob + (size_t)c * NTOK + g4 * 4) =
                *(const float4*)(Osm + c * 68 + g4 * 4);
        }
    }
}

// ---------------------------------------------------------------------------
extern "C" void kernel_launch(void* const* d_in, const int* in_sizes, int n_in,
                              void* d_out, int out_size)
{
    const float* p   = (const float*)d_in[0];
    const float* bin = (const float*)d_in[1];
    const float* Wq  = (const float*)d_in[2];
    const float* bq  = (const float*)d_in[3];
    const float* Wk  = (const float*)d_in[4];
    const float* bk  = (const float*)d_in[5];
    float* out = (float*)d_out;

    cudaFuncSetAttribute(attn_mma_kernel, cudaFuncAttributeMaxDynamicSharedMemorySize,
                         ATTN_SMEM);

    proj_kernel  <<<dim3(NTOK / 32, B_SZ, 2), 256>>>(p, bin, Wq, bq, Wk, bk);
    vconv_kernel <<<(B_SZ * CIN * NTOK) / (256 * 4), 256>>>(bin);
    attn_mma_kernel<<<dim3(NTOK / BM, B_SZ), 256, ATTN_SMEM>>>(out);
}

// round 13
// speedup vs baseline: 2.8536x; 1.0257x over previous
#include <cuda_runtime.h>
#include <cuda_bf16.h>
#include <cstdint>

#define B_SZ 8
#define CIN  256
#define COUT 128
#define NTOK 4096
#define BM   64     // queries per CTA
#define BN   64     // keys per iteration
#define NKB  (NTOK / BN)

// ---------------------------------------------------------------------------
// Scratch (static device globals; no allocation)
// ---------------------------------------------------------------------------
__device__ __nv_bfloat16 g_Qh[B_SZ * NTOK * COUT];   // [b][n][d] hi
__device__ __nv_bfloat16 g_Ql[B_SZ * NTOK * COUT];   // [b][n][d] lo
__device__ __nv_bfloat16 g_Kh[B_SZ * NTOK * COUT];   // [b][m][d] hi
__device__ __nv_bfloat16 g_Kl[B_SZ * NTOK * COUT];   // [b][m][d] lo
__device__ __nv_bfloat16 g_Vh[B_SZ * CIN * NTOK];    // [b][c][m] hi (native layout)
__device__ __nv_bfloat16 g_Vl[B_SZ * CIN * NTOK];    // [b][c][m] lo

// ---------------------------------------------------------------------------
// Warp-MMA / async-copy primitives (baseline PTX ISA -> ok for compute_103)
// ---------------------------------------------------------------------------
__device__ __forceinline__ uint32_t smem_u32(const void* p) {
    uint32_t a;
    asm("{ .reg .u64 t; cvta.to.shared.u64 t, %1; cvt.u32.u64 %0, t; }"
        : "=r"(a) : "l"(p));
    return a;
}

__device__ __forceinline__ void ldsm4(uint32_t* r, uint32_t addr) {
    asm volatile("ldmatrix.sync.aligned.m8n8.x4.shared.b16 {%0,%1,%2,%3}, [%4];"
                 : "=r"(r[0]), "=r"(r[1]), "=r"(r[2]), "=r"(r[3]) : "r"(addr));
}

// D += A * B^T   (m16n8k16, bf16 in, fp32 acc)
__device__ __forceinline__ void mma16816(float* d, const uint32_t* a, const uint32_t* b) {
    asm volatile(
        "mma.sync.aligned.m16n8k16.row.col.f32.bf16.bf16.f32 "
        "{%0,%1,%2,%3}, {%4,%5,%6,%7}, {%8,%9}, {%0,%1,%2,%3};"
        : "+f"(d[0]), "+f"(d[1]), "+f"(d[2]), "+f"(d[3])
        : "r"(a[0]), "r"(a[1]), "r"(a[2]), "r"(a[3]), "r"(b[0]), "r"(b[1]));
}

__device__ __forceinline__ uint32_t pack_bf16x2(float e0, float e1) {
    uint32_t u;
    asm("cvt.rn.bf16x2.f32 %0, %1, %2;" : "=r"(u) : "f"(e1), "f"(e0));
    return u;
}

__device__ __forceinline__ void cp16(uint32_t dst, const void* src) {
    asm volatile("cp.async.cg.shared.global [%0], [%1], 16;" :: "r"(dst), "l"(src));
}
#define CP_COMMIT() asm volatile("cp.async.commit_group;" ::: "memory")
#define CP_WAIT(n)  asm volatile("cp.async.wait_group %0;" :: "n"(n) : "memory")

// ---------------------------------------------------------------------------
// Kernel 1: projections, fp32 compute -> bf16 hi/lo split outputs (unchanged)
// ---------------------------------------------------------------------------
__global__ __launch_bounds__(256) void proj_kernel(
    const float* __restrict__ p, const float* __restrict__ bin,
    const float* __restrict__ Wq, const float* __restrict__ bq,
    const float* __restrict__ Wk, const float* __restrict__ bk)
{
    __shared__ float wst[64][129];
    __shared__ float xs [64][36];

    const int nt = blockIdx.x, bb = blockIdx.y, z = blockIdx.z;
    const float* X    = (z == 0) ? p  : bin;
    const float* W    = (z == 0) ? Wq : Wk;
    const float* bias = (z == 0) ? bq : bk;
    __nv_bfloat16* Oh = (z == 0) ? g_Qh : g_Kh;
    __nv_bfloat16* Ol = (z == 0) ? g_Ql : g_Kl;

    const int t  = threadIdx.x;
    const int d  = t & 127;
    const int n0 = (t >> 7) * 16;
    const int gn0 = nt * 32;

    float acc[16];
    const float bv = bias[d];
#pragma unroll
    for (int j = 0; j < 16; j++) acc[j] = bv;

    const float* Xb = X + (size_t)bb * CIN * NTOK;

    for (int c0 = 0; c0 < CIN; c0 += 64) {
        for (int e = t; e < 64 * 128; e += 256) {
            int cc = e & 63, dd = e >> 6;
            wst[cc][dd] = W[dd * CIN + c0 + cc];
        }
        for (int e = t; e < 64 * 32; e += 256) {
            int cc = e >> 5, nn = e & 31;
            xs[cc][nn] = Xb[(size_t)(c0 + cc) * NTOK + gn0 + nn];
        }
        __syncthreads();
#pragma unroll 8
        for (int cc = 0; cc < 64; cc++) {
            const float w = wst[cc][d];
            const float4* xr = (const float4*)&xs[cc][n0];
#pragma unroll
            for (int j4 = 0; j4 < 4; j4++) {
                float4 xv = xr[j4];
                acc[j4 * 4 + 0] += w * xv.x;
                acc[j4 * 4 + 1] += w * xv.y;
                acc[j4 * 4 + 2] += w * xv.z;
                acc[j4 * 4 + 3] += w * xv.w;
            }
        }
        __syncthreads();
    }

    const size_t ob = (size_t)bb * NTOK * COUT;
#pragma unroll
    for (int j = 0; j < 16; j++) {
        float v = acc[j];
        __nv_bfloat16 h = __float2bfloat16(v);
        __nv_bfloat16 l = __float2bfloat16(v - __bfloat162float(h));
        size_t idx = ob + (size_t)(gn0 + n0 + j) * COUT + d;
        Oh[idx] = h;
        Ol[idx] = l;
    }
}

// ---------------------------------------------------------------------------
// Kernel 2: V hi/lo split (unchanged)
// ---------------------------------------------------------------------------
__global__ __launch_bounds__(256) void vconv_kernel(const float* __restrict__ bin)
{
    size_t i = ((size_t)blockIdx.x * 256 + threadIdx.x) * 4;
    float4 v = *(const float4*)(bin + i);
    __nv_bfloat16 hx = __float2bfloat16(v.x);
    __nv_bfloat16 hy = __float2bfloat16(v.y);
    __nv_bfloat16 hz = __float2bfloat16(v.z);
    __nv_bfloat16 hw = __float2bfloat16(v.w);
    __nv_bfloat16 lx = __float2bfloat16(v.x - __bfloat162float(hx));
    __nv_bfloat16 ly = __float2bfloat16(v.y - __bfloat162float(hy));
    __nv_bfloat16 lz = __float2bfloat16(v.z - __bfloat162float(hz));
    __nv_bfloat16 lw = __float2bfloat16(v.w - __bfloat162float(hw));
    __nv_bfloat162* Vh2 = (__nv_bfloat162*)(g_Vh + i);
    __nv_bfloat162* Vl2 = (__nv_bfloat162*)(g_Vl + i);
    Vh2[0] = __halves2bfloat162(hx, hy);
    Vh2[1] = __halves2bfloat162(hz, hw);
    Vl2[0] = __halves2bfloat162(lx, ly);
    Vl2[1] = __halves2bfloat162(lz, lw);
}

// ---------------------------------------------------------------------------
// Kernel 3: warp-MMA flash attention; K AND V double-buffered, both
// prefetched one full iteration ahead. Merged hi/lo rows:
//   K row (key):      [hi 256B | lo 256B | pad 16B]  stride 528
//   V/P row:          [hi 128B | lo 128B | pad 16B]  stride 272
// (strides == 16 mod 128 -> ldmatrix conflict-free, same shift rate as before)
// exp via MUFU (__expf) instead of FMA-pipe polynomial.
// ---------------------------------------------------------------------------
#define KSTR   528
#define VSTR   272
#define SM_K0  0                      // 64*528 = 33792
#define SM_K1  33792
#define SM_V0  67584                  // 256*272 = 69632
#define SM_V1  137216
#define SM_P   206848                 // 64*272 = 17408
#define SM_LS  224256                 // L[2][64] = 512B
#define ATTN_SMEM 224768
// prologue Q staging / epilogue O staging borrow the V region:
#define SM_QS  SM_V0                  // 64*528 = 33792
#define SM_OS  SM_V0                  // 256 rows x 272B = 69632

__global__ __launch_bounds__(256, 1) void attn_mma_kernel(float* __restrict__ out)
{
    extern __shared__ char sm[];
    const uint32_t smb = smem_u32(sm);

    const int t    = threadIdx.x;
    const int wid  = t >> 5, lane = t & 31;
    const int bb   = blockIdx.y;
    const int n0   = blockIdx.x * BM;

    const int qg = wid & 3;          // QK: 16 q rows each
    const int kg = wid >> 2;         // QK: 32 keys each
    const int qg2 = wid >> 2;        // PV: 32 q rows each
    const int cg  = wid & 3;         // PV: 64 value-channels each

    const int g  = lane >> 2, tq = lane & 3;
    const uint32_t rowp  = (lane & 7) + ((lane >> 4) << 3);
    const uint32_t koff  = ((lane >> 3) & 1) * 16;
    const uint32_t arow  = (lane & 15);
    const uint32_t akoff = (lane >> 4) * 16;

    const __nv_bfloat16* Khg = g_Kh + (size_t)bb * NTOK * COUT;
    const __nv_bfloat16* Klg = g_Kl + (size_t)bb * NTOK * COUT;

    // ---- issue K[0] (overlaps Q staging) ----
    for (int e = t; e < 64 * 16; e += 256) {
        int r = e >> 4, c = e & 15;
        uint32_t d = smb + SM_K0 + r * KSTR + c * 16;
        cp16(d,       Khg + e * 8);
        cp16(d + 256, Klg + e * 8);
    }
    CP_COMMIT();

    // ---- stage Q into (borrowed) V0 region, merged-row layout ----
    {
        const uint4* Qh4 = (const uint4*)(g_Qh + ((size_t)bb * NTOK + n0) * COUT);
        const uint4* Ql4 = (const uint4*)(g_Ql + ((size_t)bb * NTOK + n0) * COUT);
        for (int e = t; e < 64 * 16; e += 256) {
            int r = e >> 4, c = e & 15;
            *(uint4*)(sm + SM_QS + r * KSTR + c * 16)       = Qh4[e];
            *(uint4*)(sm + SM_QS + r * KSTR + c * 16 + 256) = Ql4[e];
        }
    }
    __syncthreads();

    uint32_t qfh[8][4], qfl[8][4];
#pragma unroll
    for (int ks = 0; ks < 8; ks++) {
        uint32_t a = smb + SM_QS + (qg * 16 + arow) * KSTR + ks * 32 + akoff;
        ldsm4(qfh[ks], a);
        ldsm4(qfl[ks], a + 256);
    }
    __syncthreads();                 // all Q reads done; V0 region reusable

    // ---- issue V[0] into V buf0 ----
    for (int e = t; e < 256 * 8; e += 256) {
        int r = e >> 3, c8 = e & 7;
        size_t gi = ((size_t)bb * CIN + r) * NTOK + c8 * 8;
        uint32_t d = smb + SM_V0 + r * VSTR + c8 * 16;
        cp16(d,       g_Vh + gi);
        cp16(d + 128, g_Vl + gi);
    }
    CP_COMMIT();

    float of[2][8][4];
#pragma unroll
    for (int mt = 0; mt < 2; mt++)
#pragma unroll
        for (int nt = 0; nt < 8; nt++)
#pragma unroll
            for (int j = 0; j < 4; j++) of[mt][nt][j] = 0.f;

    float Lacc0 = 0.f, Lacc1 = 0.f;

    for (int kb = 0; kb < NKB; kb++) {
        const uint32_t kcur = smb + ((kb & 1) ? SM_K1 : SM_K0);
        const uint32_t vcur = smb + ((kb & 1) ? SM_V1 : SM_V0);

        CP_WAIT(0);          // K[kb] + V[kb] arrived (this thread)
        __syncthreads();     // visible to all; prev PV reads of other bufs done

        // ---- issue {K[kb+1], V[kb+1]} into the other buffers ----
        if (kb + 1 < NKB) {
            const uint32_t knxt = smb + (((kb + 1) & 1) ? SM_K1 : SM_K0);
            const uint32_t vnxt = smb + (((kb + 1) & 1) ? SM_V1 : SM_V0);
            const int m1 = (kb + 1) * BN;
            const __nv_bfloat16* kh = Khg + (size_t)m1 * COUT;
            const __nv_bfloat16* kl = Klg + (size_t)m1 * COUT;
            for (int e = t; e < 64 * 16; e += 256) {
                int r = e >> 4, c = e & 15;
                uint32_t d = knxt + r * KSTR + c * 16;
                cp16(d,       kh + e * 8);
                cp16(d + 256, kl + e * 8);
            }
            for (int e = t; e < 256 * 8; e += 256) {
                int r = e >> 3, c8 = e & 7;
                size_t gi = ((size_t)bb * CIN + r) * NTOK + m1 + c8 * 8;
                uint32_t d = vnxt + r * VSTR + c8 * 16;
                cp16(d,       g_Vh + gi);
                cp16(d + 128, g_Vl + gi);
            }
            CP_COMMIT();
        }

        // ---- QK: S[16q x 32k] = Qh*Kh + Qh*Kl + Ql*Kh (fp32 acc) ----
        float sf[4][4];
#pragma unroll
        for (int nt = 0; nt < 4; nt++)
#pragma unroll
            for (int j = 0; j < 4; j++) sf[nt][j] = 0.f;

#pragma unroll
        for (int ks = 0; ks < 8; ks++) {
            uint32_t b0h[4], b1h[4], b0l[4], b1l[4];
            uint32_t a0 = kcur + (kg * 32 + rowp) * KSTR + ks * 32 + koff;
            uint32_t a1 = kcur + (kg * 32 + 16 + rowp) * KSTR + ks * 32 + koff;
            ldsm4(b0h, a0);        ldsm4(b1h, a1);
            ldsm4(b0l, a0 + 256);  ldsm4(b1l, a1 + 256);

            mma16816(sf[0], qfh[ks], b0h + 0); mma16816(sf[1], qfh[ks], b0h + 2);
            mma16816(sf[2], qfh[ks], b1h + 0); mma16816(sf[3], qfh[ks], b1h + 2);
            mma16816(sf[0], qfh[ks], b0l + 0); mma16816(sf[1], qfh[ks], b0l + 2);
            mma16816(sf[2], qfh[ks], b1l + 0); mma16816(sf[3], qfh[ks], b1l + 2);
            mma16816(sf[0], qfl[ks], b0h + 0); mma16816(sf[1], qfl[ks], b0h + 2);
            mma16816(sf[2], qfl[ks], b1h + 0); mma16816(sf[3], qfl[ks], b1h + 2);
        }

        // ---- exp (MUFU), L accumulate, P -> smem bf16 hi/lo merged rows ----
        {
            const int r0 = qg * 16 + g, r1 = r0 + 8;
#pragma unroll
            for (int nt = 0; nt < 4; nt++) {
                float e00 = __expf(sf[nt][0]);
                float e01 = __expf(sf[nt][1]);
                float e10 = __expf(sf[nt][2]);
                float e11 = __expf(sf[nt][3]);
                Lacc0 += e00 + e01;
                Lacc1 += e10 + e11;
                const int cbyte = (kg * 32 + nt * 8 + 2 * tq) * 2;
                uint32_t h0 = pack_bf16x2(e00, e01);
                uint32_t h1 = pack_bf16x2(e10, e11);
                float l00 = e00 - __uint_as_float(h0 << 16);
                float l01 = e01 - __uint_as_float(h0 & 0xFFFF0000u);
                float l10 = e10 - __uint_as_float(h1 << 16);
                float l11 = e11 - __uint_as_float(h1 & 0xFFFF0000u);
                *(uint32_t*)(sm + SM_P + r0 * VSTR + cbyte)       = h0;
                *(uint32_t*)(sm + SM_P + r1 * VSTR + cbyte)       = h1;
                *(uint32_t*)(sm + SM_P + r0 * VSTR + cbyte + 128) = pack_bf16x2(l00, l01);
                *(uint32_t*)(sm + SM_P + r1 * VSTR + cbyte + 128) = pack_bf16x2(l10, l11);
            }
        }
        __syncthreads();     // P visible; V[kb] already waited at top

        // ---- PV: O[32q x 64c] += Ph*Vh + Ph*Vl + Pl*Vh ----
#pragma unroll
        for (int kk = 0; kk < 4; kk++) {
            uint32_t ah[2][4], al[2][4];
#pragma unroll
            for (int mt = 0; mt < 2; mt++) {
                uint32_t a = smb + SM_P + (qg2 * 32 + mt * 16 + arow) * VSTR + kk * 32 + akoff;
                ldsm4(ah[mt], a);
                ldsm4(al[mt], a + 128);
            }
#pragma unroll
            for (int pp = 0; pp < 4; pp++) {
                uint32_t vh[4], vl[4];
                uint32_t a = vcur + (cg * 64 + pp * 16 + rowp) * VSTR + kk * 32 + koff;
                ldsm4(vh, a);
                ldsm4(vl, a + 128);
#pragma unroll
                for (int mt = 0; mt < 2; mt++) {
                    mma16816(of[mt][2 * pp],     ah[mt], vh + 0);
                    mma16816(of[mt][2 * pp + 1], ah[mt], vh + 2);
                    mma16816(of[mt][2 * pp],     ah[mt], vl + 0);
                    mma16816(of[mt][2 * pp + 1], ah[mt], vl + 2);
                    mma16816(of[mt][2 * pp],     al[mt], vh + 0);
                    mma16816(of[mt][2 * pp + 1], al[mt], vh + 2);
                }
            }
        }
    }

    // ---- L reduction ----
    Lacc0 += __shfl_xor_sync(0xffffffffu, Lacc0, 1);
    Lacc0 += __shfl_xor_sync(0xffffffffu, Lacc0, 2);
    Lacc1 += __shfl_xor_sync(0xffffffffu, Lacc1, 1);
    Lacc1 += __shfl_xor_sync(0xffffffffu, Lacc1, 2);
    float* Ls = (float*)(sm + SM_LS);          // [2][64]
    if (tq == 0) {
        Ls[kg * 64 + qg * 16 + g]     = Lacc0;
        Ls[kg * 64 + qg * 16 + g + 8] = Lacc1;
    }
    __syncthreads();

    // ---- epilogue: normalize, stage O[c][n] in (borrowed) V region ----
    {
        float* Osm = (float*)(sm + SM_OS);     // 256 rows x 68 floats (272B)
        const int r0 = qg2 * 32 + g;
#pragma unroll
        for (int mt = 0; mt < 2; mt++) {
            const int ra = r0 + mt * 16, rb = ra + 8;
            const float ia = 1.0f / (Ls[ra] + Ls[64 + ra]);
            const float ib = 1.0f / (Ls[rb] + Ls[64 + rb]);
#pragma unroll
            for (int nt = 0; nt < 8; nt++) {
                const int c0 = cg * 64 + nt * 8 + 2 * tq;
                Osm[(c0)     * 68 + ra] = of[mt][nt][0] * ia;
                Osm[(c0 + 1) * 68 + ra] = of[mt][nt][1] * ia;
                Osm[(c0)     * 68 + rb] = of[mt][nt][2] * ib;
                Osm[(c0 + 1) * 68 + rb] = of[mt][nt][3] * ib;
            }
        }
    }
    __syncthreads();

    // ---- coalesced store: out[b][c][n0..n0+63] ----
    {
        const float* Osm = (const float*)(sm + SM_OS);
        float* ob = out + (size_t)bb * CIN * NTOK + n0;
        for (int e = t; e < 256 * 16; e += 256) {
            int c = e >> 4, g4 = e & 15;
            *(float4*)(ob + (size_t)c * NTOK + g4 * 4) =
                *(const float4*)(Osm + c * 68 + g4 * 4);
        }
    }
}

// ---------------------------------------------------------------------------
extern "C" void kernel_launch(void* const* d_in, const int* in_sizes, int n_in,
                              void* d_out, int out_size)
{
    const float* p   = (const float*)d_in[0];
    const float* bin = (const float*)d_in[1];
    const float* Wq  = (const float*)d_in[2];
    const float* bq  = (const float*)d_in[3];
    const float* Wk  = (const float*)d_in[4];
    const float* bk  = (const float*)d_in[5];
    float* out = (float*)d_out;

    cudaFuncSetAttribute(attn_mma_kernel, cudaFuncAttributeMaxDynamicSharedMemorySize,
                         ATTN_SMEM);

    proj_kernel  <<<dim3(NTOK / 32, B_SZ, 2), 256>>>(p, bin, Wq, bq, Wk, bk);
    vconv_kernel <<<(B_SZ * CIN * NTOK) / (256 * 4), 256>>>(bin);
    attn_mma_kernel<<<dim3(NTOK / BM, B_SZ), 256, ATTN_SMEM>>>(out);
}

// round 14
// speedup vs baseline: 3.1111x; 1.0902x over previous
#include <cuda_runtime.h>
#include <cuda_bf16.h>
#include <cstdint>

#define B_SZ 8
#define CIN  256
#define COUT 128
#define NTOK 4096
#define BM   64     // queries per CTA
#define BN   64     // keys per iteration
#define NKB  (NTOK / BN)

// ---------------------------------------------------------------------------
// Scratch (static device globals; no allocation)
// ---------------------------------------------------------------------------
__device__ __nv_bfloat16 g_Qh[B_SZ * NTOK * COUT];   // [b][n][d] hi
__device__ __nv_bfloat16 g_Ql[B_SZ * NTOK * COUT];   // [b][n][d] lo
__device__ __nv_bfloat16 g_Kh[B_SZ * NTOK * COUT];   // [b][m][d] hi
__device__ __nv_bfloat16 g_Kl[B_SZ * NTOK * COUT];   // [b][m][d] lo
__device__ __nv_bfloat16 g_Vh[B_SZ * CIN * NTOK];    // [b][c][m] hi (native layout)
__device__ __nv_bfloat16 g_Vl[B_SZ * CIN * NTOK];    // [b][c][m] lo

// ---------------------------------------------------------------------------
// Warp-MMA / async-copy primitives (baseline PTX ISA -> ok for compute_103)
// ---------------------------------------------------------------------------
__device__ __forceinline__ uint32_t smem_u32(const void* p) {
    uint32_t a;
    asm("{ .reg .u64 t; cvta.to.shared.u64 t, %1; cvt.u32.u64 %0, t; }"
        : "=r"(a) : "l"(p));
    return a;
}

__device__ __forceinline__ void ldsm4(uint32_t* r, uint32_t addr) {
    asm volatile("ldmatrix.sync.aligned.m8n8.x4.shared.b16 {%0,%1,%2,%3}, [%4];"
                 : "=r"(r[0]), "=r"(r[1]), "=r"(r[2]), "=r"(r[3]) : "r"(addr));
}

// transposed ldmatrix: [k][n]-stored tile + trans == [n][k] B-fragment
__device__ __forceinline__ void ldsm4t(uint32_t* r, uint32_t addr) {
    asm volatile("ldmatrix.sync.aligned.m8n8.x4.trans.shared.b16 {%0,%1,%2,%3}, [%4];"
                 : "=r"(r[0]), "=r"(r[1]), "=r"(r[2]), "=r"(r[3]) : "r"(addr));
}

// D += A * B^T   (m16n8k16, bf16 in, fp32 acc)
__device__ __forceinline__ void mma16816(float* d, const uint32_t* a, const uint32_t* b) {
    asm volatile(
        "mma.sync.aligned.m16n8k16.row.col.f32.bf16.bf16.f32 "
        "{%0,%1,%2,%3}, {%4,%5,%6,%7}, {%8,%9}, {%0,%1,%2,%3};"
        : "+f"(d[0]), "+f"(d[1]), "+f"(d[2]), "+f"(d[3])
        : "r"(a[0]), "r"(a[1]), "r"(a[2]), "r"(a[3]), "r"(b[0]), "r"(b[1]));
}

__device__ __forceinline__ uint32_t pack_bf16x2(float e0, float e1) {
    uint32_t u;
    asm("cvt.rn.bf16x2.f32 %0, %1, %2;" : "=r"(u) : "f"(e1), "f"(e0));
    return u;
}

__device__ __forceinline__ void cp16(uint32_t dst, const void* src) {
    asm volatile("cp.async.cg.shared.global [%0], [%1], 16;" :: "r"(dst), "l"(src));
}
#define CP_COMMIT() asm volatile("cp.async.commit_group;" ::: "memory")
#define CP_WAIT(n)  asm volatile("cp.async.wait_group %0;" :: "n"(n) : "memory")

// ---------------------------------------------------------------------------
// Kernel 1: HMMA projections. D[128d x 64n] = W(128x256) * X(256c x 64n) + b
// Split-bf16 3-term: Wh*Xh + Wh*Xl + Wl*Xh (fp32 acc), converted in-kernel.
// X kept [c][n] (coalesced); B operand produced via ldmatrix.trans.
// grid (NTOK/64, B, 2), block 256 (8 warps, warp w owns d rows 16w..16w+15).
// ---------------------------------------------------------------------------
#define PJ_WS   0                    // W chunk: 128 rows x [hi128|lo128|pad16]
#define PJ_XS   34816                // X chunk: 64 rows x [hi128|lo128|pad16]
#define PJ_SMEM (34816 + 17408)     // 52224
// epilogue D staging reuses the W region (after final sync):
#define PJ_DH   0                    // 64 rows x 272 (128 d bf16 + pad)
#define PJ_DL   17408

__global__ __launch_bounds__(256) void proj_mma_kernel(
    const float* __restrict__ p, const float* __restrict__ bin,
    const float* __restrict__ Wq, const float* __restrict__ bq,
    const float* __restrict__ Wk, const float* __restrict__ bk)
{
    extern __shared__ char sm[];
    const uint32_t smb = smem_u32(sm);

    const int nt64 = blockIdx.x, bb = blockIdx.y, z = blockIdx.z;
    const float* X    = (z == 0) ? p  : bin;
    const float* W    = (z == 0) ? Wq : Wk;
    const float* bias = (z == 0) ? bq : bk;
    __nv_bfloat16* Oh = (z == 0) ? g_Qh : g_Kh;
    __nv_bfloat16* Ol = (z == 0) ? g_Ql : g_Kl;

    const int t = threadIdx.x;
    const int wid = t >> 5, lane = t & 31;
    const int g = lane >> 2, tq = lane & 3;
    const uint32_t arow  = lane & 15;
    const uint32_t akoff = (lane >> 4) * 16;
    // trans-B addressing: lane -> (c row within k16, n-group select)
    const int crow = (lane & 7) + ((lane >> 3) & 1) * 8;
    const int ngsel = (lane >> 4);            // 0: n-grp lo, 1: n-grp hi (+8)

    const float* Xb = X + (size_t)bb * CIN * NTOK + nt64 * 64;

    float df[8][4];
#pragma unroll
    for (int j = 0; j < 8; j++)
#pragma unroll
        for (int i = 0; i < 4; i++) df[j][i] = 0.f;

    for (int c0 = 0; c0 < CIN; c0 += 64) {
        // ---- stage W chunk [128d x 64c] fp32 -> bf16 hi/lo merged rows ----
        for (int e = t; e < 128 * 16; e += 256) {
            int dd = e >> 4, c4 = e & 15;
            float4 wv = *(const float4*)(W + dd * CIN + c0 + c4 * 4);
            uint32_t h0 = pack_bf16x2(wv.x, wv.y);
            uint32_t h1 = pack_bf16x2(wv.z, wv.w);
            float l00 = wv.x - __uint_as_float(h0 << 16);
            float l01 = wv.y - __uint_as_float(h0 & 0xFFFF0000u);
            float l10 = wv.z - __uint_as_float(h1 << 16);
            float l11 = wv.w - __uint_as_float(h1 & 0xFFFF0000u);
            uint32_t base = (uint32_t)(dd * 272 + c4 * 8);
            *(uint32_t*)(sm + PJ_WS + base)           = h0;
            *(uint32_t*)(sm + PJ_WS + base + 4)       = h1;
            *(uint32_t*)(sm + PJ_WS + base + 128)     = pack_bf16x2(l00, l01);
            *(uint32_t*)(sm + PJ_WS + base + 132)     = pack_bf16x2(l10, l11);
        }
        // ---- stage X chunk [64c x 64n] fp32 -> bf16 hi/lo merged rows ----
        for (int e = t; e < 64 * 16; e += 256) {
            int cc = e >> 4, n4 = e & 15;
            float4 xv = *(const float4*)(Xb + (size_t)(c0 + cc) * NTOK + n4 * 4);
            uint32_t h0 = pack_bf16x2(xv.x, xv.y);
            uint32_t h1 = pack_bf16x2(xv.z, xv.w);
            float l00 = xv.x - __uint_as_float(h0 << 16);
            float l01 = xv.y - __uint_as_float(h0 & 0xFFFF0000u);
            float l10 = xv.z - __uint_as_float(h1 << 16);
            float l11 = xv.w - __uint_as_float(h1 & 0xFFFF0000u);
            uint32_t base = (uint32_t)(cc * 272 + n4 * 8);
            *(uint32_t*)(sm + PJ_XS + base)           = h0;
            *(uint32_t*)(sm + PJ_XS + base + 4)       = h1;
            *(uint32_t*)(sm + PJ_XS + base + 128)     = pack_bf16x2(l00, l01);
            *(uint32_t*)(sm + PJ_XS + base + 132)     = pack_bf16x2(l10, l11);
        }
        __syncthreads();

        // ---- MMA: 4 k16 steps x 8 n-groups x 3 terms ----
#pragma unroll
        for (int ks = 0; ks < 4; ks++) {
            uint32_t awh[4], awl[4];
            uint32_t aaddr = smb + PJ_WS + (wid * 16 + arow) * 272 + ks * 32 + akoff;
            ldsm4(awh, aaddr);
            ldsm4(awl, aaddr + 128);
#pragma unroll
            for (int n2 = 0; n2 < 4; n2++) {
                uint32_t bxh[4], bxl[4];
                uint32_t baddr = smb + PJ_XS + (ks * 16 + crow) * 272
                               + (n2 * 16 + ngsel * 8) * 2;
                ldsm4t(bxh, baddr);
                ldsm4t(bxl, baddr + 128);
                mma16816(df[n2 * 2],     awh, bxh + 0);
                mma16816(df[n2 * 2 + 1], awh, bxh + 2);
                mma16816(df[n2 * 2],     awh, bxl + 0);
                mma16816(df[n2 * 2 + 1], awh, bxl + 2);
                mma16816(df[n2 * 2],     awl, bxh + 0);
                mma16816(df[n2 * 2 + 1], awl, bxh + 2);
            }
        }
        __syncthreads();
    }

    // ---- epilogue: +bias, hi/lo split, stage [n][d], coalesced write ----
    {
        const float b0 = bias[wid * 16 + g];
        const float b1 = bias[wid * 16 + g + 8];
        const int d0 = wid * 16 + g, d1 = d0 + 8;
#pragma unroll
        for (int nt = 0; nt < 8; nt++) {
            const int n = nt * 8 + 2 * tq;
            float v00 = df[nt][0] + b0, v01 = df[nt][1] + b0;
            float v10 = df[nt][2] + b1, v11 = df[nt][3] + b1;
            uint32_t h0 = pack_bf16x2(v00, v01);   // (n, n+1) at row d0
            uint32_t h1 = pack_bf16x2(v10, v11);   // (n, n+1) at row d1
            float l00 = v00 - __uint_as_float(h0 << 16);
            float l01 = v01 - __uint_as_float(h0 & 0xFFFF0000u);
            float l10 = v10 - __uint_as_float(h1 << 16);
            float l11 = v11 - __uint_as_float(h1 & 0xFFFF0000u);
            uint32_t lp0 = pack_bf16x2(l00, l01);
            uint32_t lp1 = pack_bf16x2(l10, l11);
            // store per-element into [n][d] staging (2B each)
            *(__nv_bfloat16*)(sm + PJ_DH + (n)     * 272 + d0 * 2) = __ushort_as_bfloat16((uint16_t)(h0 & 0xFFFF));
            *(__nv_bfloat16*)(sm + PJ_DH + (n + 1) * 272 + d0 * 2) = __ushort_as_bfloat16((uint16_t)(h0 >> 16));
            *(__nv_bfloat16*)(sm + PJ_DH + (n)     * 272 + d1 * 2) = __ushort_as_bfloat16((uint16_t)(h1 & 0xFFFF));
            *(__nv_bfloat16*)(sm + PJ_DH + (n + 1) * 272 + d1 * 2) = __ushort_as_bfloat16((uint16_t)(h1 >> 16));
            *(__nv_bfloat16*)(sm + PJ_DL + (n)     * 272 + d0 * 2) = __ushort_as_bfloat16((uint16_t)(lp0 & 0xFFFF));
            *(__nv_bfloat16*)(sm + PJ_DL + (n + 1) * 272 + d0 * 2) = __ushort_as_bfloat16((uint16_t)(lp0 >> 16));
            *(__nv_bfloat16*)(sm + PJ_DL + (n)     * 272 + d1 * 2) = __ushort_as_bfloat16((uint16_t)(lp1 & 0xFFFF));
            *(__nv_bfloat16*)(sm + PJ_DL + (n + 1) * 272 + d1 * 2) = __ushort_as_bfloat16((uint16_t)(lp1 >> 16));
        }
    }
    __syncthreads();

    {
        const size_t ob = ((size_t)bb * NTOK + nt64 * 64) * COUT;
        for (int e = t; e < 64 * 16; e += 256) {
            int r = e >> 4, c16 = e & 15;
            *(uint4*)(Oh + ob + (size_t)r * COUT + c16 * 8) =
                *(const uint4*)(sm + PJ_DH + r * 272 + c16 * 16);
            *(uint4*)(Ol + ob + (size_t)r * COUT + c16 * 8) =
                *(const uint4*)(sm + PJ_DL + r * 272 + c16 * 16);
        }
    }
}

// ---------------------------------------------------------------------------
// Kernel 2: V hi/lo split (unchanged)
// ---------------------------------------------------------------------------
__global__ __launch_bounds__(256) void vconv_kernel(const float* __restrict__ bin)
{
    size_t i = ((size_t)blockIdx.x * 256 + threadIdx.x) * 4;
    float4 v = *(const float4*)(bin + i);
    __nv_bfloat16 hx = __float2bfloat16(v.x);
    __nv_bfloat16 hy = __float2bfloat16(v.y);
    __nv_bfloat16 hz = __float2bfloat16(v.z);
    __nv_bfloat16 hw = __float2bfloat16(v.w);
    __nv_bfloat16 lx = __float2bfloat16(v.x - __bfloat162float(hx));
    __nv_bfloat16 ly = __float2bfloat16(v.y - __bfloat162float(hy));
    __nv_bfloat16 lz = __float2bfloat16(v.z - __bfloat162float(hz));
    __nv_bfloat16 lw = __float2bfloat16(v.w - __bfloat162float(hw));
    __nv_bfloat162* Vh2 = (__nv_bfloat162*)(g_Vh + i);
    __nv_bfloat162* Vl2 = (__nv_bfloat162*)(g_Vl + i);
    Vh2[0] = __halves2bfloat162(hx, hy);
    Vh2[1] = __halves2bfloat162(hz, hw);
    Vl2[0] = __halves2bfloat162(lx, ly);
    Vl2[1] = __halves2bfloat162(lz, lw);
}

// ---------------------------------------------------------------------------
// Kernel 3: warp-MMA flash attention (unchanged from Round 13 winner)
// ---------------------------------------------------------------------------
#define KSTR   528
#define VSTR   272
#define SM_K0  0
#define SM_K1  33792
#define SM_V0  67584
#define SM_V1  137216
#define SM_P   206848
#define SM_LS  224256
#define ATTN_SMEM 224768
#define SM_QS  SM_V0
#define SM_OS  SM_V0

__global__ __launch_bounds__(256, 1) void attn_mma_kernel(float* __restrict__ out)
{
    extern __shared__ char sm[];
    const uint32_t smb = smem_u32(sm);

    const int t    = threadIdx.x;
    const int wid  = t >> 5, lane = t & 31;
    const int bb   = blockIdx.y;
    const int n0   = blockIdx.x * BM;

    const int qg = wid & 3;
    const int kg = wid >> 2;
    const int qg2 = wid >> 2;
    const int cg  = wid & 3;

    const int g  = lane >> 2, tq = lane & 3;
    const uint32_t rowp  = (lane & 7) + ((lane >> 4) << 3);
    const uint32_t koff  = ((lane >> 3) & 1) * 16;
    const uint32_t arow  = (lane & 15);
    const uint32_t akoff = (lane >> 4) * 16;

    const __nv_bfloat16* Khg = g_Kh + (size_t)bb * NTOK * COUT;
    const __nv_bfloat16* Klg = g_Kl + (size_t)bb * NTOK * COUT;

    for (int e = t; e < 64 * 16; e += 256) {
        int r = e >> 4, c = e & 15;
        uint32_t d = smb + SM_K0 + r * KSTR + c * 16;
        cp16(d,       Khg + e * 8);
        cp16(d + 256, Klg + e * 8);
    }
    CP_COMMIT();

    {
        const uint4* Qh4 = (const uint4*)(g_Qh + ((size_t)bb * NTOK + n0) * COUT);
        const uint4* Ql4 = (const uint4*)(g_Ql + ((size_t)bb * NTOK + n0) * COUT);
        for (int e = t; e < 64 * 16; e += 256) {
            int r = e >> 4, c = e & 15;
            *(uint4*)(sm + SM_QS + r * KSTR + c * 16)       = Qh4[e];
            *(uint4*)(sm + SM_QS + r * KSTR + c * 16 + 256) = Ql4[e];
        }
    }
    __syncthreads();

    uint32_t qfh[8][4], qfl[8][4];
#pragma unroll
    for (int ks = 0; ks < 8; ks++) {
        uint32_t a = smb + SM_QS + (qg * 16 + arow) * KSTR + ks * 32 + akoff;
        ldsm4(qfh[ks], a);
        ldsm4(qfl[ks], a + 256);
    }
    __syncthreads();

    for (int e = t; e < 256 * 8; e += 256) {
        int r = e >> 3, c8 = e & 7;
        size_t gi = ((size_t)bb * CIN + r) * NTOK + c8 * 8;
        uint32_t d = smb + SM_V0 + r * VSTR + c8 * 16;
        cp16(d,       g_Vh + gi);
        cp16(d + 128, g_Vl + gi);
    }
    CP_COMMIT();

    float of[2][8][4];
#pragma unroll
    for (int mt = 0; mt < 2; mt++)
#pragma unroll
        for (int nt = 0; nt < 8; nt++)
#pragma unroll
            for (int j = 0; j < 4; j++) of[mt][nt][j] = 0.f;

    float Lacc0 = 0.f, Lacc1 = 0.f;

    for (int kb = 0; kb < NKB; kb++) {
        const uint32_t kcur = smb + ((kb & 1) ? SM_K1 : SM_K0);
        const uint32_t vcur = smb + ((kb & 1) ? SM_V1 : SM_V0);

        CP_WAIT(0);
        __syncthreads();

        if (kb + 1 < NKB) {
            const uint32_t knxt = smb + (((kb + 1) & 1) ? SM_K1 : SM_K0);
            const uint32_t vnxt = smb + (((kb + 1) & 1) ? SM_V1 : SM_V0);
            const int m1 = (kb + 1) * BN;
            const __nv_bfloat16* kh = Khg + (size_t)m1 * COUT;
            const __nv_bfloat16* kl = Klg + (size_t)m1 * COUT;
            for (int e = t; e < 64 * 16; e += 256) {
                int r = e >> 4, c = e & 15;
                uint32_t d = knxt + r * KSTR + c * 16;
                cp16(d,       kh + e * 8);
                cp16(d + 256, kl + e * 8);
            }
            for (int e = t; e < 256 * 8; e += 256) {
                int r = e >> 3, c8 = e & 7;
                size_t gi = ((size_t)bb * CIN + r) * NTOK + m1 + c8 * 8;
                uint32_t d = vnxt + r * VSTR + c8 * 16;
                cp16(d,       g_Vh + gi);
                cp16(d + 128, g_Vl + gi);
            }
            CP_COMMIT();
        }

        float sf[4][4];
#pragma unroll
        for (int nt = 0; nt < 4; nt++)
#pragma unroll
            for (int j = 0; j < 4; j++) sf[nt][j] = 0.f;

#pragma unroll
        for (int ks = 0; ks < 8; ks++) {
            uint32_t b0h[4], b1h[4], b0l[4], b1l[4];
            uint32_t a0 = kcur + (kg * 32 + rowp) * KSTR + ks * 32 + koff;
            uint32_t a1 = kcur + (kg * 32 + 16 + rowp) * KSTR + ks * 32 + koff;
            ldsm4(b0h, a0);        ldsm4(b1h, a1);
            ldsm4(b0l, a0 + 256);  ldsm4(b1l, a1 + 256);

            mma16816(sf[0], qfh[ks], b0h + 0); mma16816(sf[1], qfh[ks], b0h + 2);
            mma16816(sf[2], qfh[ks], b1h + 0); mma16816(sf[3], qfh[ks], b1h + 2);
            mma16816(sf[0], qfh[ks], b0l + 0); mma16816(sf[1], qfh[ks], b0l + 2);
            mma16816(sf[2], qfh[ks], b1l + 0); mma16816(sf[3], qfh[ks], b1l + 2);
            mma16816(sf[0], qfl[ks], b0h + 0); mma16816(sf[1], qfl[ks], b0h + 2);
            mma16816(sf[2], qfl[ks], b1h + 0); mma16816(sf[3], qfl[ks], b1h + 2);
        }

        {
            const int r0 = qg * 16 + g, r1 = r0 + 8;
#pragma unroll
            for (int nt = 0; nt < 4; nt++) {
                float e00 = __expf(sf[nt][0]);
                float e01 = __expf(sf[nt][1]);
                float e10 = __expf(sf[nt][2]);
                float e11 = __expf(sf[nt][3]);
                Lacc0 += e00 + e01;
                Lacc1 += e10 + e11;
                const int cbyte = (kg * 32 + nt * 8 + 2 * tq) * 2;
                uint32_t h0 = pack_bf16x2(e00, e01);
                uint32_t h1 = pack_bf16x2(e10, e11);
                float l00 = e00 - __uint_as_float(h0 << 16);
                float l01 = e01 - __uint_as_float(h0 & 0xFFFF0000u);
                float l10 = e10 - __uint_as_float(h1 << 16);
                float l11 = e11 - __uint_as_float(h1 & 0xFFFF0000u);
                *(uint32_t*)(sm + SM_P + r0 * VSTR + cbyte)       = h0;
                *(uint32_t*)(sm + SM_P + r1 * VSTR + cbyte)       = h1;
                *(uint32_t*)(sm + SM_P + r0 * VSTR + cbyte + 128) = pack_bf16x2(l00, l01);
                *(uint32_t*)(sm + SM_P + r1 * VSTR + cbyte + 128) = pack_bf16x2(l10, l11);
            }
        }
        __syncthreads();

#pragma unroll
        for (int kk = 0; kk < 4; kk++) {
            uint32_t ah[2][4], al[2][4];
#pragma unroll
            for (int mt = 0; mt < 2; mt++) {
                uint32_t a = smb + SM_P + (qg2 * 32 + mt * 16 + arow) * VSTR + kk * 32 + akoff;
                ldsm4(ah[mt], a);
                ldsm4(al[mt], a + 128);
            }
#pragma unroll
            for (int pp = 0; pp < 4; pp++) {
                uint32_t vh[4], vl[4];
                uint32_t a = vcur + (cg * 64 + pp * 16 + rowp) * VSTR + kk * 32 + koff;
                ldsm4(vh, a);
                ldsm4(vl, a + 128);
#pragma unroll
                for (int mt = 0; mt < 2; mt++) {
                    mma16816(of[mt][2 * pp],     ah[mt], vh + 0);
                    mma16816(of[mt][2 * pp + 1], ah[mt], vh + 2);
                    mma16816(of[mt][2 * pp],     ah[mt], vl + 0);
                    mma16816(of[mt][2 * pp + 1], ah[mt], vl + 2);
                    mma16816(of[mt][2 * pp],     al[mt], vh + 0);
                    mma16816(of[mt][2 * pp + 1], al[mt], vh + 2);
                }
            }
        }
    }

    Lacc0 += __shfl_xor_sync(0xffffffffu, Lacc0, 1);
    Lacc0 += __shfl_xor_sync(0xffffffffu, Lacc0, 2);
    Lacc1 += __shfl_xor_sync(0xffffffffu, Lacc1, 1);
    Lacc1 += __shfl_xor_sync(0xffffffffu, Lacc1, 2);
    float* Ls = (float*)(sm + SM_LS);
    if (tq == 0) {
        Ls[kg * 64 + qg * 16 + g]     = Lacc0;
        Ls[kg * 64 + qg * 16 + g + 8] = Lacc1;
    }
    __syncthreads();

    {
        float* Osm = (float*)(sm + SM_OS);
        const int r0 = qg2 * 32 + g;
#pragma unroll
        for (int mt = 0; mt < 2; mt++) {
            const int ra = r0 + mt * 16, rb = ra + 8;
            const float ia = 1.0f / (Ls[ra] + Ls[64 + ra]);
            const float ib = 1.0f / (Ls[rb] + Ls[64 + rb]);
#pragma unroll
            for (int nt = 0; nt < 8; nt++) {
                const int c0 = cg * 64 + nt * 8 + 2 * tq;
                Osm[(c0)     * 68 + ra] = of[mt][nt][0] * ia;
                Osm[(c0 + 1) * 68 + ra] = of[mt][nt][1] * ia;
                Osm[(c0)     * 68 + rb] = of[mt][nt][2] * ib;
                Osm[(c0 + 1) * 68 + rb] = of[mt][nt][3] * ib;
            }
        }
    }
    __syncthreads();

    {
        const float* Osm = (const float*)(sm + SM_OS);
        float* ob = out + (size_t)bb * CIN * NTOK + n0;
        for (int e = t; e < 256 * 16; e += 256) {
            int c = e >> 4, g4 = e & 15;
            *(float4*)(ob + (size_t)c * NTOK + g4 * 4) =
                *(const float4*)(Osm + c * 68 + g4 * 4);
        }
    }
}

// ---------------------------------------------------------------------------
extern "C" void kernel_launch(void* const* d_in, const int* in_sizes, int n_in,
                              void* d_out, int out_size)
{
    const float* p   = (const float*)d_in[0];
    const float* bin = (const float*)d_in[1];
    const float* Wq  = (const float*)d_in[2];
    const float* bq  = (const float*)d_in[3];
    const float* Wk  = (const float*)d_in[4];
    const float* bk  = (const float*)d_in[5];
    float* out = (float*)d_out;

    cudaFuncSetAttribute(proj_mma_kernel, cudaFuncAttributeMaxDynamicSharedMemorySize,
                         PJ_SMEM);
    cudaFuncSetAttribute(attn_mma_kernel, cudaFuncAttributeMaxDynamicSharedMemorySize,
                         ATTN_SMEM);

    proj_mma_kernel<<<dim3(NTOK / 64, B_SZ, 2), 256, PJ_SMEM>>>(p, bin, Wq, bq, Wk, bk);
    vconv_kernel   <<<(B_SZ * CIN * NTOK) / (256 * 4), 256>>>(bin);
    attn_mma_kernel<<<dim3(NTOK / BM, B_SZ), 256, ATTN_SMEM>>>(out);
}

// round 15
// speedup vs baseline: 3.4406x; 1.1059x over previous
#include <cuda_runtime.h>
#include <cuda_bf16.h>
#include <cstdint>

#define B_SZ 8
#define CIN  256
#define COUT 128
#define NTOK 4096
#define BM   64     // queries per CTA
#define BN   64     // keys per iteration
#define NKB  (NTOK / BN)
#define NSPL 2              // key splits
#define NKBS (NKB / NSPL)   // key blocks per split

// ---------------------------------------------------------------------------
// Scratch (static device globals; no allocation)
// ---------------------------------------------------------------------------
__device__ __nv_bfloat16 g_Qh[B_SZ * NTOK * COUT];   // [b][n][d] hi
__device__ __nv_bfloat16 g_Ql[B_SZ * NTOK * COUT];   // [b][n][d] lo
__device__ __nv_bfloat16 g_Kh[B_SZ * NTOK * COUT];   // [b][m][d] hi
__device__ __nv_bfloat16 g_Kl[B_SZ * NTOK * COUT];   // [b][m][d] lo
__device__ __nv_bfloat16 g_Vh[B_SZ * CIN * NTOK];    // [b][c][m] hi (native layout)
__device__ __nv_bfloat16 g_Vl[B_SZ * CIN * NTOK];    // [b][c][m] lo
__device__ float g_Op[NSPL * B_SZ * CIN * NTOK];     // unnormalized O partials
__device__ float g_Lp[NSPL * B_SZ * NTOK];           // L partials

// ---------------------------------------------------------------------------
// Warp-MMA / async-copy primitives (baseline PTX ISA -> ok for compute_103)
// ---------------------------------------------------------------------------
__device__ __forceinline__ uint32_t smem_u32(const void* p) {
    uint32_t a;
    asm("{ .reg .u64 t; cvta.to.shared.u64 t, %1; cvt.u32.u64 %0, t; }"
        : "=r"(a) : "l"(p));
    return a;
}

__device__ __forceinline__ void ldsm4(uint32_t* r, uint32_t addr) {
    asm volatile("ldmatrix.sync.aligned.m8n8.x4.shared.b16 {%0,%1,%2,%3}, [%4];"
                 : "=r"(r[0]), "=r"(r[1]), "=r"(r[2]), "=r"(r[3]) : "r"(addr));
}

__device__ __forceinline__ void ldsm4t(uint32_t* r, uint32_t addr) {
    asm volatile("ldmatrix.sync.aligned.m8n8.x4.trans.shared.b16 {%0,%1,%2,%3}, [%4];"
                 : "=r"(r[0]), "=r"(r[1]), "=r"(r[2]), "=r"(r[3]) : "r"(addr));
}

// D += A * B^T   (m16n8k16, bf16 in, fp32 acc)
__device__ __forceinline__ void mma16816(float* d, const uint32_t* a, const uint32_t* b) {
    asm volatile(
        "mma.sync.aligned.m16n8k16.row.col.f32.bf16.bf16.f32 "
        "{%0,%1,%2,%3}, {%4,%5,%6,%7}, {%8,%9}, {%0,%1,%2,%3};"
        : "+f"(d[0]), "+f"(d[1]), "+f"(d[2]), "+f"(d[3])
        : "r"(a[0]), "r"(a[1]), "r"(a[2]), "r"(a[3]), "r"(b[0]), "r"(b[1]));
}

__device__ __forceinline__ uint32_t pack_bf16x2(float e0, float e1) {
    uint32_t u;
    asm("cvt.rn.bf16x2.f32 %0, %1, %2;" : "=r"(u) : "f"(e1), "f"(e0));
    return u;
}

__device__ __forceinline__ void cp16(uint32_t dst, const void* src) {
    asm volatile("cp.async.cg.shared.global [%0], [%1], 16;" :: "r"(dst), "l"(src));
}
#define CP_COMMIT() asm volatile("cp.async.commit_group;" ::: "memory")
#define CP_WAIT(n)  asm volatile("cp.async.wait_group %0;" :: "n"(n) : "memory")

// ---------------------------------------------------------------------------
// Kernel 1: HMMA projections (Round-14 winner + minBlocks=3 occupancy hint)
// ---------------------------------------------------------------------------
#define PJ_WS   0
#define PJ_XS   34816
#define PJ_SMEM (34816 + 17408)
#define PJ_DH   0
#define PJ_DL   17408

__global__ __launch_bounds__(256, 3) void proj_mma_kernel(
    const float* __restrict__ p, const float* __restrict__ bin,
    const float* __restrict__ Wq, const float* __restrict__ bq,
    const float* __restrict__ Wk, const float* __restrict__ bk)
{
    extern __shared__ char sm[];
    const uint32_t smb = smem_u32(sm);

    const int nt64 = blockIdx.x, bb = blockIdx.y, z = blockIdx.z;
    const float* X    = (z == 0) ? p  : bin;
    const float* W    = (z == 0) ? Wq : Wk;
    const float* bias = (z == 0) ? bq : bk;
    __nv_bfloat16* Oh = (z == 0) ? g_Qh : g_Kh;
    __nv_bfloat16* Ol = (z == 0) ? g_Ql : g_Kl;

    const int t = threadIdx.x;
    const int wid = t >> 5, lane = t & 31;
    const int g = lane >> 2, tq = lane & 3;
    const uint32_t arow  = lane & 15;
    const uint32_t akoff = (lane >> 4) * 16;
    const int crow = (lane & 7) + ((lane >> 3) & 1) * 8;
    const int ngsel = (lane >> 4);

    const float* Xb = X + (size_t)bb * CIN * NTOK + nt64 * 64;

    float df[8][4];
#pragma unroll
    for (int j = 0; j < 8; j++)
#pragma unroll
        for (int i = 0; i < 4; i++) df[j][i] = 0.f;

    for (int c0 = 0; c0 < CIN; c0 += 64) {
        for (int e = t; e < 128 * 16; e += 256) {
            int dd = e >> 4, c4 = e & 15;
            float4 wv = *(const float4*)(W + dd * CIN + c0 + c4 * 4);
            uint32_t h0 = pack_bf16x2(wv.x, wv.y);
            uint32_t h1 = pack_bf16x2(wv.z, wv.w);
            float l00 = wv.x - __uint_as_float(h0 << 16);
            float l01 = wv.y - __uint_as_float(h0 & 0xFFFF0000u);
            float l10 = wv.z - __uint_as_float(h1 << 16);
            float l11 = wv.w - __uint_as_float(h1 & 0xFFFF0000u);
            uint32_t base = (uint32_t)(dd * 272 + c4 * 8);
            *(uint32_t*)(sm + PJ_WS + base)       = h0;
            *(uint32_t*)(sm + PJ_WS + base + 4)   = h1;
            *(uint32_t*)(sm + PJ_WS + base + 128) = pack_bf16x2(l00, l01);
            *(uint32_t*)(sm + PJ_WS + base + 132) = pack_bf16x2(l10, l11);
        }
        for (int e = t; e < 64 * 16; e += 256) {
            int cc = e >> 4, n4 = e & 15;
            float4 xv = *(const float4*)(Xb + (size_t)(c0 + cc) * NTOK + n4 * 4);
            uint32_t h0 = pack_bf16x2(xv.x, xv.y);
            uint32_t h1 = pack_bf16x2(xv.z, xv.w);
            float l00 = xv.x - __uint_as_float(h0 << 16);
            float l01 = xv.y - __uint_as_float(h0 & 0xFFFF0000u);
            float l10 = xv.z - __uint_as_float(h1 << 16);
            float l11 = xv.w - __uint_as_float(h1 & 0xFFFF0000u);
            uint32_t base = (uint32_t)(cc * 272 + n4 * 8);
            *(uint32_t*)(sm + PJ_XS + base)       = h0;
            *(uint32_t*)(sm + PJ_XS + base + 4)   = h1;
            *(uint32_t*)(sm + PJ_XS + base + 128) = pack_bf16x2(l00, l01);
            *(uint32_t*)(sm + PJ_XS + base + 132) = pack_bf16x2(l10, l11);
        }
        __syncthreads();

#pragma unroll
        for (int ks = 0; ks < 4; ks++) {
            uint32_t awh[4], awl[4];
            uint32_t aaddr = smb + PJ_WS + (wid * 16 + arow) * 272 + ks * 32 + akoff;
            ldsm4(awh, aaddr);
            ldsm4(awl, aaddr + 128);
#pragma unroll
            for (int n2 = 0; n2 < 4; n2++) {
                uint32_t bxh[4], bxl[4];
                uint32_t baddr = smb + PJ_XS + (ks * 16 + crow) * 272
                               + (n2 * 16 + ngsel * 8) * 2;
                ldsm4t(bxh, baddr);
                ldsm4t(bxl, baddr + 128);
                mma16816(df[n2 * 2],     awh, bxh + 0);
                mma16816(df[n2 * 2 + 1], awh, bxh + 2);
                mma16816(df[n2 * 2],     awh, bxl + 0);
                mma16816(df[n2 * 2 + 1], awh, bxl + 2);
                mma16816(df[n2 * 2],     awl, bxh + 0);
                mma16816(df[n2 * 2 + 1], awl, bxh + 2);
            }
        }
        __syncthreads();
    }

    {
        const float b0 = bias[wid * 16 + g];
        const float b1 = bias[wid * 16 + g + 8];
        const int d0 = wid * 16 + g, d1 = d0 + 8;
#pragma unroll
        for (int nt = 0; nt < 8; nt++) {
            const int n = nt * 8 + 2 * tq;
            float v00 = df[nt][0] + b0, v01 = df[nt][1] + b0;
            float v10 = df[nt][2] + b1, v11 = df[nt][3] + b1;
            uint32_t h0 = pack_bf16x2(v00, v01);
            uint32_t h1 = pack_bf16x2(v10, v11);
            float l00 = v00 - __uint_as_float(h0 << 16);
            float l01 = v01 - __uint_as_float(h0 & 0xFFFF0000u);
            float l10 = v10 - __uint_as_float(h1 << 16);
            float l11 = v11 - __uint_as_float(h1 & 0xFFFF0000u);
            uint32_t lp0 = pack_bf16x2(l00, l01);
            uint32_t lp1 = pack_bf16x2(l10, l11);
            *(__nv_bfloat16*)(sm + PJ_DH + (n)     * 272 + d0 * 2) = __ushort_as_bfloat16((uint16_t)(h0 & 0xFFFF));
            *(__nv_bfloat16*)(sm + PJ_DH + (n + 1) * 272 + d0 * 2) = __ushort_as_bfloat16((uint16_t)(h0 >> 16));
            *(__nv_bfloat16*)(sm + PJ_DH + (n)     * 272 + d1 * 2) = __ushort_as_bfloat16((uint16_t)(h1 & 0xFFFF));
            *(__nv_bfloat16*)(sm + PJ_DH + (n + 1) * 272 + d1 * 2) = __ushort_as_bfloat16((uint16_t)(h1 >> 16));
            *(__nv_bfloat16*)(sm + PJ_DL + (n)     * 272 + d0 * 2) = __ushort_as_bfloat16((uint16_t)(lp0 & 0xFFFF));
            *(__nv_bfloat16*)(sm + PJ_DL + (n + 1) * 272 + d0 * 2) = __ushort_as_bfloat16((uint16_t)(lp0 >> 16));
            *(__nv_bfloat16*)(sm + PJ_DL + (n)     * 272 + d1 * 2) = __ushort_as_bfloat16((uint16_t)(lp1 & 0xFFFF));
            *(__nv_bfloat16*)(sm + PJ_DL + (n + 1) * 272 + d1 * 2) = __ushort_as_bfloat16((uint16_t)(lp1 >> 16));
        }
    }
    __syncthreads();

    {
        const size_t ob = ((size_t)bb * NTOK + nt64 * 64) * COUT;
        for (int e = t; e < 64 * 16; e += 256) {
            int r = e >> 4, c16 = e & 15;
            *(uint4*)(Oh + ob + (size_t)r * COUT + c16 * 8) =
                *(const uint4*)(sm + PJ_DH + r * 272 + c16 * 16);
            *(uint4*)(Ol + ob + (size_t)r * COUT + c16 * 8) =
                *(const uint4*)(sm + PJ_DL + r * 272 + c16 * 16);
        }
    }
}

// ---------------------------------------------------------------------------
// Kernel 2: V hi/lo split (unchanged)
// ---------------------------------------------------------------------------
__global__ __launch_bounds__(256) void vconv_kernel(const float* __restrict__ bin)
{
    size_t i = ((size_t)blockIdx.x * 256 + threadIdx.x) * 4;
    float4 v = *(const float4*)(bin + i);
    __nv_bfloat16 hx = __float2bfloat16(v.x);
    __nv_bfloat16 hy = __float2bfloat16(v.y);
    __nv_bfloat16 hz = __float2bfloat16(v.z);
    __nv_bfloat16 hw = __float2bfloat16(v.w);
    __nv_bfloat16 lx = __float2bfloat16(v.x - __bfloat162float(hx));
    __nv_bfloat16 ly = __float2bfloat16(v.y - __bfloat162float(hy));
    __nv_bfloat16 lz = __float2bfloat16(v.z - __bfloat162float(hz));
    __nv_bfloat16 lw = __float2bfloat16(v.w - __bfloat162float(hw));
    __nv_bfloat162* Vh2 = (__nv_bfloat162*)(g_Vh + i);
    __nv_bfloat162* Vl2 = (__nv_bfloat162*)(g_Vl + i);
    Vh2[0] = __halves2bfloat162(hx, hy);
    Vh2[1] = __halves2bfloat162(hz, hw);
    Vl2[0] = __halves2bfloat162(lx, ly);
    Vl2[1] = __halves2bfloat162(lz, lw);
}

// ---------------------------------------------------------------------------
// Kernel 3: warp-MMA flash attention, SPLIT-K over key halves.
// grid (NTOK/BM, B, NSPL); each CTA: 32 key blocks, writes unnormalized
// O-partial [z][b][c][n] and L-partial [z][b][n].
// ---------------------------------------------------------------------------
#define KSTR   528
#define VSTR   272
#define SM_K0  0
#define SM_K1  33792
#define SM_V0  67584
#define SM_V1  137216
#define SM_P   206848
#define SM_LS  224256
#define ATTN_SMEM 224768
#define SM_QS  SM_V0
#define SM_OS  SM_V0

__global__ __launch_bounds__(256, 1) void attn_mma_kernel()
{
    extern __shared__ char sm[];
    const uint32_t smb = smem_u32(sm);

    const int t    = threadIdx.x;
    const int wid  = t >> 5, lane = t & 31;
    const int bb   = blockIdx.y;
    const int n0   = blockIdx.x * BM;
    const int z    = blockIdx.z;
    const int kb0  = z * NKBS;

    const int qg = wid & 3;
    const int kg = wid >> 2;
    const int qg2 = wid >> 2;
    const int cg  = wid & 3;

    const int g  = lane >> 2, tq = lane & 3;
    const uint32_t rowp  = (lane & 7) + ((lane >> 4) << 3);
    const uint32_t koff  = ((lane >> 3) & 1) * 16;
    const uint32_t arow  = (lane & 15);
    const uint32_t akoff = (lane >> 4) * 16;

    const __nv_bfloat16* Khg = g_Kh + (size_t)bb * NTOK * COUT;
    const __nv_bfloat16* Klg = g_Kl + (size_t)bb * NTOK * COUT;

    // ---- issue K[kb0] (kb0 even -> buf0 matches loop parity) ----
    {
        const __nv_bfloat16* kh = Khg + (size_t)kb0 * BN * COUT;
        const __nv_bfloat16* kl = Klg + (size_t)kb0 * BN * COUT;
        for (int e = t; e < 64 * 16; e += 256) {
            int r = e >> 4, c = e & 15;
            uint32_t d = smb + SM_K0 + r * KSTR + c * 16;
            cp16(d,       kh + e * 8);
            cp16(d + 256, kl + e * 8);
        }
    }
    CP_COMMIT();

    {
        const uint4* Qh4 = (const uint4*)(g_Qh + ((size_t)bb * NTOK + n0) * COUT);
        const uint4* Ql4 = (const uint4*)(g_Ql + ((size_t)bb * NTOK + n0) * COUT);
        for (int e = t; e < 64 * 16; e += 256) {
            int r = e >> 4, c = e & 15;
            *(uint4*)(sm + SM_QS + r * KSTR + c * 16)       = Qh4[e];
            *(uint4*)(sm + SM_QS + r * KSTR + c * 16 + 256) = Ql4[e];
        }
    }
    __syncthreads();

    uint32_t qfh[8][4], qfl[8][4];
#pragma unroll
    for (int ks = 0; ks < 8; ks++) {
        uint32_t a = smb + SM_QS + (qg * 16 + arow) * KSTR + ks * 32 + akoff;
        ldsm4(qfh[ks], a);
        ldsm4(qfl[ks], a + 256);
    }
    __syncthreads();

    for (int e = t; e < 256 * 8; e += 256) {
        int r = e >> 3, c8 = e & 7;
        size_t gi = ((size_t)bb * CIN + r) * NTOK + kb0 * BN + c8 * 8;
        uint32_t d = smb + SM_V0 + r * VSTR + c8 * 16;
        cp16(d,       g_Vh + gi);
        cp16(d + 128, g_Vl + gi);
    }
    CP_COMMIT();

    float of[2][8][4];
#pragma unroll
    for (int mt = 0; mt < 2; mt++)
#pragma unroll
        for (int nt = 0; nt < 8; nt++)
#pragma unroll
            for (int j = 0; j < 4; j++) of[mt][nt][j] = 0.f;

    float Lacc0 = 0.f, Lacc1 = 0.f;

    for (int kb = kb0; kb < kb0 + NKBS; kb++) {
        const uint32_t kcur = smb + ((kb & 1) ? SM_K1 : SM_K0);
        const uint32_t vcur = smb + ((kb & 1) ? SM_V1 : SM_V0);

        CP_WAIT(0);
        __syncthreads();

        if (kb + 1 < kb0 + NKBS) {
            const uint32_t knxt = smb + (((kb + 1) & 1) ? SM_K1 : SM_K0);
            const uint32_t vnxt = smb + (((kb + 1) & 1) ? SM_V1 : SM_V0);
            const int m1 = (kb + 1) * BN;
            const __nv_bfloat16* kh = Khg + (size_t)m1 * COUT;
            const __nv_bfloat16* kl = Klg + (size_t)m1 * COUT;
            for (int e = t; e < 64 * 16; e += 256) {
                int r = e >> 4, c = e & 15;
                uint32_t d = knxt + r * KSTR + c * 16;
                cp16(d,       kh + e * 8);
                cp16(d + 256, kl + e * 8);
            }
            for (int e = t; e < 256 * 8; e += 256) {
                int r = e >> 3, c8 = e & 7;
                size_t gi = ((size_t)bb * CIN + r) * NTOK + m1 + c8 * 8;
                uint32_t d = vnxt + r * VSTR + c8 * 16;
                cp16(d,       g_Vh + gi);
                cp16(d + 128, g_Vl + gi);
            }
            CP_COMMIT();
        }

        float sf[4][4];
#pragma unroll
        for (int nt = 0; nt < 4; nt++)
#pragma unroll
            for (int j = 0; j < 4; j++) sf[nt][j] = 0.f;

#pragma unroll
        for (int ks = 0; ks < 8; ks++) {
            uint32_t b0h[4], b1h[4], b0l[4], b1l[4];
            uint32_t a0 = kcur + (kg * 32 + rowp) * KSTR + ks * 32 + koff;
            uint32_t a1 = kcur + (kg * 32 + 16 + rowp) * KSTR + ks * 32 + koff;
            ldsm4(b0h, a0);        ldsm4(b1h, a1);
            ldsm4(b0l, a0 + 256);  ldsm4(b1l, a1 + 256);

            mma16816(sf[0], qfh[ks], b0h + 0); mma16816(sf[1], qfh[ks], b0h + 2);
            mma16816(sf[2], qfh[ks], b1h + 0); mma16816(sf[3], qfh[ks], b1h + 2);
            mma16816(sf[0], qfh[ks], b0l + 0); mma16816(sf[1], qfh[ks], b0l + 2);
            mma16816(sf[2], qfh[ks], b1l + 0); mma16816(sf[3], qfh[ks], b1l + 2);
            mma16816(sf[0], qfl[ks], b0h + 0); mma16816(sf[1], qfl[ks], b0h + 2);
            mma16816(sf[2], qfl[ks], b1h + 0); mma16816(sf[3], qfl[ks], b1h + 2);
        }

        {
            const int r0 = qg * 16 + g, r1 = r0 + 8;
#pragma unroll
            for (int nt = 0; nt < 4; nt++) {
                float e00 = __expf(sf[nt][0]);
                float e01 = __expf(sf[nt][1]);
                float e10 = __expf(sf[nt][2]);
                float e11 = __expf(sf[nt][3]);
                Lacc0 += e00 + e01;
                Lacc1 += e10 + e11;
                const int cbyte = (kg * 32 + nt * 8 + 2 * tq) * 2;
                uint32_t h0 = pack_bf16x2(e00, e01);
                uint32_t h1 = pack_bf16x2(e10, e11);
                float l00 = e00 - __uint_as_float(h0 << 16);
                float l01 = e01 - __uint_as_float(h0 & 0xFFFF0000u);
                float l10 = e10 - __uint_as_float(h1 << 16);
                float l11 = e11 - __uint_as_float(h1 & 0xFFFF0000u);
                *(uint32_t*)(sm + SM_P + r0 * VSTR + cbyte)       = h0;
                *(uint32_t*)(sm + SM_P + r1 * VSTR + cbyte)       = h1;
                *(uint32_t*)(sm + SM_P + r0 * VSTR + cbyte + 128) = pack_bf16x2(l00, l01);
                *(uint32_t*)(sm + SM_P + r1 * VSTR + cbyte + 128) = pack_bf16x2(l10, l11);
            }
        }
        __syncthreads();

#pragma unroll
        for (int kk = 0; kk < 4; kk++) {
            uint32_t ah[2][4], al[2][4];
#pragma unroll
            for (int mt = 0; mt < 2; mt++) {
                uint32_t a = smb + SM_P + (qg2 * 32 + mt * 16 + arow) * VSTR + kk * 32 + akoff;
                ldsm4(ah[mt], a);
                ldsm4(al[mt], a + 128);
            }
#pragma unroll
            for (int pp = 0; pp < 4; pp++) {
                uint32_t vh[4], vl[4];
                uint32_t a = vcur + (cg * 64 + pp * 16 + rowp) * VSTR + kk * 32 + koff;
                ldsm4(vh, a);
                ldsm4(vl, a + 128);
#pragma unroll
                for (int mt = 0; mt < 2; mt++) {
                    mma16816(of[mt][2 * pp],     ah[mt], vh + 0);
                    mma16816(of[mt][2 * pp + 1], ah[mt], vh + 2);
                    mma16816(of[mt][2 * pp],     ah[mt], vl + 0);
                    mma16816(of[mt][2 * pp + 1], ah[mt], vl + 2);
                    mma16816(of[mt][2 * pp],     al[mt], vh + 0);
                    mma16816(of[mt][2 * pp + 1], al[mt], vh + 2);
                }
            }
        }
    }

    // ---- L reduction + write L-partial ----
    Lacc0 += __shfl_xor_sync(0xffffffffu, Lacc0, 1);
    Lacc0 += __shfl_xor_sync(0xffffffffu, Lacc0, 2);
    Lacc1 += __shfl_xor_sync(0xffffffffu, Lacc1, 1);
    Lacc1 += __shfl_xor_sync(0xffffffffu, Lacc1, 2);
    float* Ls = (float*)(sm + SM_LS);
    if (tq == 0) {
        Ls[kg * 64 + qg * 16 + g]     = Lacc0;
        Ls[kg * 64 + qg * 16 + g + 8] = Lacc1;
    }
    __syncthreads();
    if (t < 64)
        g_Lp[((size_t)z * B_SZ + bb) * NTOK + n0 + t] = Ls[t] + Ls[64 + t];

    // ---- epilogue: stage UNNORMALIZED O[c][n], write O-partial ----
    {
        float* Osm = (float*)(sm + SM_OS);
        const int r0 = qg2 * 32 + g;
#pragma unroll
        for (int mt = 0; mt < 2; mt++) {
            const int ra = r0 + mt * 16, rb = ra + 8;
#pragma unroll
            for (int nt = 0; nt < 8; nt++) {
                const int c0 = cg * 64 + nt * 8 + 2 * tq;
                Osm[(c0)     * 68 + ra] = of[mt][nt][0];
                Osm[(c0 + 1) * 68 + ra] = of[mt][nt][1];
                Osm[(c0)     * 68 + rb] = of[mt][nt][2];
                Osm[(c0 + 1) * 68 + rb] = of[mt][nt][3];
            }
        }
    }
    __syncthreads();

    {
        const float* Osm = (const float*)(sm + SM_OS);
        float* ob = g_Op + ((size_t)z * B_SZ + bb) * CIN * NTOK + n0;
        for (int e = t; e < 256 * 16; e += 256) {
            int c = e >> 4, g4 = e & 15;
            *(float4*)(ob + (size_t)c * NTOK + g4 * 4) =
                *(const float4*)(Osm + c * 68 + g4 * 4);
        }
    }
}

// ---------------------------------------------------------------------------
// Kernel 4: combine  out[b][c][n] = (O0+O1) / (L0+L1)
// grid 8192, block 256, float4 per thread.
// ---------------------------------------------------------------------------
__global__ __launch_bounds__(256) void combine_kernel(float* __restrict__ out)
{
    const size_t i4 = (size_t)blockIdx.x * 256 + threadIdx.x;
    const size_t e  = i4 * 4;
    const int n  = (int)(e & (NTOK - 1));
    const int bc = (int)(e >> 12);
    const int b  = bc >> 8;

    const float4 o0 = *(const float4*)(g_Op + e);
    const float4 o1 = *(const float4*)(g_Op + (size_t)B_SZ * CIN * NTOK + e);
    const float4 l0 = *(const float4*)(g_Lp + (size_t)b * NTOK + n);
    const float4 l1 = *(const float4*)(g_Lp + ((size_t)B_SZ + b) * NTOK + n);

    float4 r;
    r.x = (o0.x + o1.x) / (l0.x + l1.x);
    r.y = (o0.y + o1.y) / (l0.y + l1.y);
    r.z = (o0.z + o1.z) / (l0.z + l1.z);
    r.w = (o0.w + o1.w) / (l0.w + l1.w);
    *(float4*)(out + e) = r;
}

// ---------------------------------------------------------------------------
extern "C" void kernel_launch(void* const* d_in, const int* in_sizes, int n_in,
                              void* d_out, int out_size)
{
    const float* p   = (const float*)d_in[0];
    const float* bin = (const float*)d_in[1];
    const float* Wq  = (const float*)d_in[2];
    const float* bq  = (const float*)d_in[3];
    const float* Wk  = (const float*)d_in[4];
    const float* bk  = (const float*)d_in[5];
    float* out = (float*)d_out;

    cudaFuncSetAttribute(proj_mma_kernel, cudaFuncAttributeMaxDynamicSharedMemorySize,
                         PJ_SMEM);
    cudaFuncSetAttribute(attn_mma_kernel, cudaFuncAttributeMaxDynamicSharedMemorySize,
                         ATTN_SMEM);

    proj_mma_kernel<<<dim3(NTOK / 64, B_SZ, 2), 256, PJ_SMEM>>>(p, bin, Wq, bq, Wk, bk);
    vconv_kernel   <<<(B_SZ * CIN * NTOK) / (256 * 4), 256>>>(bin);
    attn_mma_kernel<<<dim3(NTOK / BM, B_SZ, NSPL), 256, ATTN_SMEM>>>();
    combine_kernel <<<(B_SZ * CIN * NTOK) / (256 * 4), 256>>>(out);
}

// round 17
// speedup vs baseline: 5.0740x; 1.4747x over previous
#include <cuda_runtime.h>
#include <cuda_bf16.h>
#include <cuda_fp16.h>
#include <cstdint>

#define B_SZ 8
#define CIN  256
#define COUT 128
#define NTOK 4096
#define BM   64     // queries per CTA
#define BN   64     // keys per iteration
#define NKB  (NTOK / BN)
#define NSPL 2              // key splits
#define NKBS (NKB / NSPL)   // key blocks per split

// ---------------------------------------------------------------------------
// Scratch (static device globals; no allocation)
// ---------------------------------------------------------------------------
__device__ __nv_bfloat16 g_Qh[B_SZ * NTOK * COUT];   // [b][n][d] hi
__device__ __nv_bfloat16 g_Ql[B_SZ * NTOK * COUT];   // [b][n][d] lo
__device__ __nv_bfloat16 g_Kh[B_SZ * NTOK * COUT];   // [b][m][d] hi
__device__ __nv_bfloat16 g_Kl[B_SZ * NTOK * COUT];   // [b][m][d] lo
__device__ __half        g_Vf[B_SZ * CIN * NTOK];    // [b][c][m] fp16 (native layout)
__device__ float g_Op[NSPL * B_SZ * CIN * NTOK];     // unnormalized O partials (scaled)
__device__ float g_Lp[NSPL * B_SZ * NTOK];           // L partials (same scale)

// ---------------------------------------------------------------------------
// Warp-MMA / async-copy primitives (baseline PTX ISA -> ok for compute_103)
// ---------------------------------------------------------------------------
__device__ __forceinline__ uint32_t smem_u32(const void* p) {
    uint32_t a;
    asm("{ .reg .u64 t; cvta.to.shared.u64 t, %1; cvt.u32.u64 %0, t; }"
        : "=r"(a) : "l"(p));
    return a;
}

__device__ __forceinline__ void ldsm4(uint32_t* r, uint32_t addr) {
    asm volatile("ldmatrix.sync.aligned.m8n8.x4.shared.b16 {%0,%1,%2,%3}, [%4];"
                 : "=r"(r[0]), "=r"(r[1]), "=r"(r[2]), "=r"(r[3]) : "r"(addr));
}

__device__ __forceinline__ void ldsm4t(uint32_t* r, uint32_t addr) {
    asm volatile("ldmatrix.sync.aligned.m8n8.x4.trans.shared.b16 {%0,%1,%2,%3}, [%4];"
                 : "=r"(r[0]), "=r"(r[1]), "=r"(r[2]), "=r"(r[3]) : "r"(addr));
}

// D += A * B^T   (m16n8k16, bf16 in, fp32 acc)
__device__ __forceinline__ void mma16816(float* d, const uint32_t* a, const uint32_t* b) {
    asm volatile(
        "mma.sync.aligned.m16n8k16.row.col.f32.bf16.bf16.f32 "
        "{%0,%1,%2,%3}, {%4,%5,%6,%7}, {%8,%9}, {%0,%1,%2,%3};"
        : "+f"(d[0]), "+f"(d[1]), "+f"(d[2]), "+f"(d[3])
        : "r"(a[0]), "r"(a[1]), "r"(a[2]), "r"(a[3]), "r"(b[0]), "r"(b[1]));
}

// D += A * B^T   (m16n8k16, fp16 in, fp32 acc)
__device__ __forceinline__ void mma16816h(float* d, const uint32_t* a, const uint32_t* b) {
    asm volatile(
        "mma.sync.aligned.m16n8k16.row.col.f32.f16.f16.f32 "
        "{%0,%1,%2,%3}, {%4,%5,%6,%7}, {%8,%9}, {%0,%1,%2,%3};"
        : "+f"(d[0]), "+f"(d[1]), "+f"(d[2]), "+f"(d[3])
        : "r"(a[0]), "r"(a[1]), "r"(a[2]), "r"(a[3]), "r"(b[0]), "r"(b[1]));
}

__device__ __forceinline__ uint32_t pack_bf16x2(float e0, float e1) {
    uint32_t u;
    asm("cvt.rn.bf16x2.f32 %0, %1, %2;" : "=r"(u) : "f"(e1), "f"(e0));
    return u;
}

__device__ __forceinline__ uint32_t pack_f16x2(float e0, float e1) {
    uint32_t u;
    asm("cvt.rn.f16x2.f32 %0, %1, %2;" : "=r"(u) : "f"(e1), "f"(e0));
    return u;
}

__device__ __forceinline__ void cp16(uint32_t dst, const void* src) {
    asm volatile("cp.async.cg.shared.global [%0], [%1], 16;" :: "r"(dst), "l"(src));
}
#define CP_COMMIT() asm volatile("cp.async.commit_group;" ::: "memory")
#define CP_WAIT(n)  asm volatile("cp.async.wait_group %0;" :: "n"(n) : "memory")

// static softmax prescale: exp(s - 20*ln2) keeps P in fp16 range; the scale
// cancels exactly in O/L.
#define EXPC 13.8629436f

// ---------------------------------------------------------------------------
// Kernel 1: HMMA projections, tile 32n (grid 2048) + occupancy 4.
// ---------------------------------------------------------------------------
#define PJ_WS   0                    // W chunk: 128 rows x 272
#define PJ_XS   34816                // X chunk: 64 rows x 144 (hi64|lo64|pad16)
#define PJ_SMEM (34816 + 9216)       // 44032
#define PJ_DH   0                    // epilogue: 32 rows x 272 (hi)
#define PJ_DL   8704                 //           32 rows x 272 (lo)

__global__ __launch_bounds__(256, 4) void proj_mma_kernel(
    const float* __restrict__ p, const float* __restrict__ bin,
    const float* __restrict__ Wq, const float* __restrict__ bq,
    const float* __restrict__ Wk, const float* __restrict__ bk)
{
    extern __shared__ char sm[];
    const uint32_t smb = smem_u32(sm);

    const int nt32 = blockIdx.x, bb = blockIdx.y, z = blockIdx.z;
    const float* X    = (z == 0) ? p  : bin;
    const float* W    = (z == 0) ? Wq : Wk;
    const float* bias = (z == 0) ? bq : bk;
    __nv_bfloat16* Oh = (z == 0) ? g_Qh : g_Kh;
    __nv_bfloat16* Ol = (z == 0) ? g_Ql : g_Kl;

    const int t = threadIdx.x;
    const int wid = t >> 5, lane = t & 31;
    const int g = lane >> 2, tq = lane & 3;
    const uint32_t arow  = lane & 15;
    const uint32_t akoff = (lane >> 4) * 16;
    const int crow = (lane & 7) + ((lane >> 3) & 1) * 8;
    const int ngsel = (lane >> 4);

    const float* Xb = X + (size_t)bb * CIN * NTOK + nt32 * 32;

    float df[4][4];
#pragma unroll
    for (int j = 0; j < 4; j++)
#pragma unroll
        for (int i = 0; i < 4; i++) df[j][i] = 0.f;

    for (int c0 = 0; c0 < CIN; c0 += 64) {
        // stage W chunk [128d x 64c] -> bf16 hi/lo merged rows (272)
        for (int e = t; e < 128 * 16; e += 256) {
            int dd = e >> 4, c4 = e & 15;
            float4 wv = *(const float4*)(W + dd * CIN + c0 + c4 * 4);
            uint32_t h0 = pack_bf16x2(wv.x, wv.y);
            uint32_t h1 = pack_bf16x2(wv.z, wv.w);
            float l00 = wv.x - __uint_as_float(h0 << 16);
            float l01 = wv.y - __uint_as_float(h0 & 0xFFFF0000u);
            float l10 = wv.z - __uint_as_float(h1 << 16);
            float l11 = wv.w - __uint_as_float(h1 & 0xFFFF0000u);
            uint32_t base = (uint32_t)(dd * 272 + c4 * 8);
            *(uint32_t*)(sm + PJ_WS + base)       = h0;
            *(uint32_t*)(sm + PJ_WS + base + 4)   = h1;
            *(uint32_t*)(sm + PJ_WS + base + 128) = pack_bf16x2(l00, l01);
            *(uint32_t*)(sm + PJ_WS + base + 132) = pack_bf16x2(l10, l11);
        }
        // stage X chunk [64c x 32n] -> bf16 hi/lo merged rows (144)
        for (int e = t; e < 64 * 8; e += 256) {
            int cc = e >> 3, n4 = e & 7;
            float4 xv = *(const float4*)(Xb + (size_t)(c0 + cc) * NTOK + n4 * 4);
            uint32_t h0 = pack_bf16x2(xv.x, xv.y);
            uint32_t h1 = pack_bf16x2(xv.z, xv.w);
            float l00 = xv.x - __uint_as_float(h0 << 16);
            float l01 = xv.y - __uint_as_float(h0 & 0xFFFF0000u);
            float l10 = xv.z - __uint_as_float(h1 << 16);
            float l11 = xv.w - __uint_as_float(h1 & 0xFFFF0000u);
            uint32_t base = (uint32_t)(cc * 144 + n4 * 8);
            *(uint32_t*)(sm + PJ_XS + base)      = h0;
            *(uint32_t*)(sm + PJ_XS + base + 4)  = h1;
            *(uint32_t*)(sm + PJ_XS + base + 64) = pack_bf16x2(l00, l01);
            *(uint32_t*)(sm + PJ_XS + base + 68) = pack_bf16x2(l10, l11);
        }
        __syncthreads();

#pragma unroll
        for (int ks = 0; ks < 4; ks++) {
            uint32_t awh[4], awl[4];
            uint32_t aaddr = smb + PJ_WS + (wid * 16 + arow) * 272 + ks * 32 + akoff;
            ldsm4(awh, aaddr);
            ldsm4(awl, aaddr + 128);
#pragma unroll
            for (int n2 = 0; n2 < 2; n2++) {
                uint32_t bxh[4], bxl[4];
                uint32_t baddr = smb + PJ_XS + (ks * 16 + crow) * 144
                               + (n2 * 16 + ngsel * 8) * 2;
                ldsm4t(bxh, baddr);
                ldsm4t(bxl, baddr + 64);
                mma16816(df[n2 * 2],     awh, bxh + 0);
                mma16816(df[n2 * 2 + 1], awh, bxh + 2);
                mma16816(df[n2 * 2],     awh, bxl + 0);
                mma16816(df[n2 * 2 + 1], awh, bxl + 2);
                mma16816(df[n2 * 2],     awl, bxh + 0);
                mma16816(df[n2 * 2 + 1], awl, bxh + 2);
            }
        }
        __syncthreads();
    }

    // epilogue: +bias, hi/lo split, stage [n][d], coalesced write
    {
        const float b0 = bias[wid * 16 + g];
        const float b1 = bias[wid * 16 + g + 8];
        const int d0 = wid * 16 + g, d1 = d0 + 8;
#pragma unroll
        for (int nt = 0; nt < 4; nt++) {
            const int n = nt * 8 + 2 * tq;
            float v00 = df[nt][0] + b0, v01 = df[nt][1] + b0;
            float v10 = df[nt][2] + b1, v11 = df[nt][3] + b1;
            uint32_t h0 = pack_bf16x2(v00, v01);
            uint32_t h1 = pack_bf16x2(v10, v11);
            float l00 = v00 - __uint_as_float(h0 << 16);
            float l01 = v01 - __uint_as_float(h0 & 0xFFFF0000u);
            float l10 = v10 - __uint_as_float(h1 << 16);
            float l11 = v11 - __uint_as_float(h1 & 0xFFFF0000u);
            uint32_t lp0 = pack_bf16x2(l00, l01);
            uint32_t lp1 = pack_bf16x2(l10, l11);
            *(__nv_bfloat16*)(sm + PJ_DH + (n)     * 272 + d0 * 2) = __ushort_as_bfloat16((uint16_t)(h0 & 0xFFFF));
            *(__nv_bfloat16*)(sm + PJ_DH + (n + 1) * 272 + d0 * 2) = __ushort_as_bfloat16((uint16_t)(h0 >> 16));
            *(__nv_bfloat16*)(sm + PJ_DH + (n)     * 272 + d1 * 2) = __ushort_as_bfloat16((uint16_t)(h1 & 0xFFFF));
            *(__nv_bfloat16*)(sm + PJ_DH + (n + 1) * 272 + d1 * 2) = __ushort_as_bfloat16((uint16_t)(h1 >> 16));
            *(__nv_bfloat16*)(sm + PJ_DL + (n)     * 272 + d0 * 2) = __ushort_as_bfloat16((uint16_t)(lp0 & 0xFFFF));
            *(__nv_bfloat16*)(sm + PJ_DL + (n + 1) * 272 + d0 * 2) = __ushort_as_bfloat16((uint16_t)(lp0 >> 16));
            *(__nv_bfloat16*)(sm + PJ_DL + (n)     * 272 + d1 * 2) = __ushort_as_bfloat16((uint16_t)(lp1 & 0xFFFF));
            *(__nv_bfloat16*)(sm + PJ_DL + (n + 1) * 272 + d1 * 2) = __ushort_as_bfloat16((uint16_t)(lp1 >> 16));
        }
    }
    __syncthreads();

    {
        const size_t ob = ((size_t)bb * NTOK + nt32 * 32) * COUT;
        for (int e = t; e < 32 * 16; e += 256) {
            int r = e >> 4, c16 = e & 15;
            *(uint4*)(Oh + ob + (size_t)r * COUT + c16 * 8) =
                *(const uint4*)(sm + PJ_DH + r * 272 + c16 * 16);
            *(uint4*)(Ol + ob + (size_t)r * COUT + c16 * 8) =
                *(const uint4*)(sm + PJ_DL + r * 272 + c16 * 16);
        }
    }
}

// ---------------------------------------------------------------------------
// Kernel 2: V -> fp16 (single), native [b][c][m] layout
// ---------------------------------------------------------------------------
__global__ __launch_bounds__(256) void vconv_kernel(const float* __restrict__ bin)
{
    size_t i = ((size_t)blockIdx.x * 256 + threadIdx.x) * 4;
    float4 v = *(const float4*)(bin + i);
    __half2* V2 = (__half2*)(g_Vf + i);
    V2[0] = __floats2half2_rn(v.x, v.y);
    V2[1] = __floats2half2_rn(v.z, v.w);
}

// ---------------------------------------------------------------------------
// Kernel 3: flash attention, split-K. QK = split-bf16 3-term (unchanged);
// PV = SINGLE fp16 MMA (P prescaled by 2^-20; scale cancels in O/L).
// K + V double-buffered via cp.async one iteration ahead.
//   K row: [hi 256B | lo 256B | pad 16]  stride 528
//   V row: [128B fp16 | pad 16]          stride 144
//   P row: [128B fp16 | pad 16]          stride 144
// ---------------------------------------------------------------------------
#define KSTR   528
#define VSTR   144
#define SM_K0  0                     // 64*528 = 33792
#define SM_K1  33792
#define SM_V0  67584                 // 256*144 = 36864
#define SM_V1  104448
#define SM_P   141312                // 64*144 = 9216
#define SM_LS  150528                // L[2][64]
#define ATTN_SMEM 151040
#define SM_QS  SM_V0                 // prologue Q staging (64*528 = 33792 fits V0)
#define SM_OS  SM_V0                 // epilogue O staging (256*272 = 69632 fits V0+V1)

__global__ __launch_bounds__(256, 1) void attn_mma_kernel()
{
    extern __shared__ char sm[];
    const uint32_t smb = smem_u32(sm);

    const int t    = threadIdx.x;
    const int wid  = t >> 5, lane = t & 31;
    const int bb   = blockIdx.y;
    const int n0   = blockIdx.x * BM;
    const int z    = blockIdx.z;
    const int kb0  = z * NKBS;

    const int qg = wid & 3;          // QK: 16 q rows each
    const int kg = wid >> 2;         // QK: 32 keys each
    const int qg2 = wid >> 2;        // PV: 32 q rows each
    const int cg  = wid & 3;         // PV: 64 value-channels each

    const int g  = lane >> 2, tq = lane & 3;
    const uint32_t rowp  = (lane & 7) + ((lane >> 4) << 3);
    const uint32_t koff  = ((lane >> 3) & 1) * 16;
    const uint32_t arow  = (lane & 15);
    const uint32_t akoff = (lane >> 4) * 16;

    const __nv_bfloat16* Khg = g_Kh + (size_t)bb * NTOK * COUT;
    const __nv_bfloat16* Klg = g_Kl + (size_t)bb * NTOK * COUT;
    const __half*        Vfg = g_Vf + (size_t)bb * CIN * NTOK;

    // ---- issue K[kb0] (kb0 even -> buf0 matches loop parity) ----
    {
        const __nv_bfloat16* kh = Khg + (size_t)kb0 * BN * COUT;
        const __nv_bfloat16* kl = Klg + (size_t)kb0 * BN * COUT;
        for (int e = t; e < 64 * 16; e += 256) {
            int r = e >> 4, c = e & 15;
            uint32_t d = smb + SM_K0 + r * KSTR + c * 16;
            cp16(d,       kh + e * 8);
            cp16(d + 256, kl + e * 8);
        }
    }
    CP_COMMIT();

    // ---- stage Q, load Q fragments to regs ----
    {
        const uint4* Qh4 = (const uint4*)(g_Qh + ((size_t)bb * NTOK + n0) * COUT);
        const uint4* Ql4 = (const uint4*)(g_Ql + ((size_t)bb * NTOK + n0) * COUT);
        for (int e = t; e < 64 * 16; e += 256) {
            int r = e >> 4, c = e & 15;
            *(uint4*)(sm + SM_QS + r * KSTR + c * 16)       = Qh4[e];
            *(uint4*)(sm + SM_QS + r * KSTR + c * 16 + 256) = Ql4[e];
        }
    }
    __syncthreads();

    uint32_t qfh[8][4], qfl[8][4];
#pragma unroll
    for (int ks = 0; ks < 8; ks++) {
        uint32_t a = smb + SM_QS + (qg * 16 + arow) * KSTR + ks * 32 + akoff;
        ldsm4(qfh[ks], a);
        ldsm4(qfl[ks], a + 256);
    }
    __syncthreads();

    // ---- issue V[kb0] ----
    for (int e = t; e < 256 * 8; e += 256) {
        int r = e >> 3, c8 = e & 7;
        cp16(smb + SM_V0 + r * VSTR + c8 * 16,
             Vfg + (size_t)r * NTOK + kb0 * BN + c8 * 8);
    }
    CP_COMMIT();

    float of[2][8][4];
#pragma unroll
    for (int mt = 0; mt < 2; mt++)
#pragma unroll
        for (int nt = 0; nt < 8; nt++)
#pragma unroll
            for (int j = 0; j < 4; j++) of[mt][nt][j] = 0.f;

    float Lacc0 = 0.f, Lacc1 = 0.f;

    for (int kb = kb0; kb < kb0 + NKBS; kb++) {
        const uint32_t kcur = smb + ((kb & 1) ? SM_K1 : SM_K0);
        const uint32_t vcur = smb + ((kb & 1) ? SM_V1 : SM_V0);

        CP_WAIT(0);
        __syncthreads();

        // ---- issue {K[kb+1], V[kb+1]} ----
        if (kb + 1 < kb0 + NKBS) {
            const uint32_t knxt = smb + (((kb + 1) & 1) ? SM_K1 : SM_K0);
            const uint32_t vnxt = smb + (((kb + 1) & 1) ? SM_V1 : SM_V0);
            const int m1 = (kb + 1) * BN;
            const __nv_bfloat16* kh = Khg + (size_t)m1 * COUT;
            const __nv_bfloat16* kl = Klg + (size_t)m1 * COUT;
            for (int e = t; e < 64 * 16; e += 256) {
                int r = e >> 4, c = e & 15;
                uint32_t d = knxt + r * KSTR + c * 16;
                cp16(d,       kh + e * 8);
                cp16(d + 256, kl + e * 8);
            }
            for (int e = t; e < 256 * 8; e += 256) {
                int r = e >> 3, c8 = e & 7;
                cp16(vnxt + r * VSTR + c8 * 16,
                     Vfg + (size_t)r * NTOK + m1 + c8 * 8);
            }
            CP_COMMIT();
        }

        // ---- QK: S = Qh*Kh + Qh*Kl + Ql*Kh (bf16, fp32 acc) ----
        float sf[4][4];
#pragma unroll
        for (int nt = 0; nt < 4; nt++)
#pragma unroll
            for (int j = 0; j < 4; j++) sf[nt][j] = 0.f;

#pragma unroll
        for (int ks = 0; ks < 8; ks++) {
            uint32_t b0h[4], b1h[4], b0l[4], b1l[4];
            uint32_t a0 = kcur + (kg * 32 + rowp) * KSTR + ks * 32 + koff;
            uint32_t a1 = kcur + (kg * 32 + 16 + rowp) * KSTR + ks * 32 + koff;
            ldsm4(b0h, a0);        ldsm4(b1h, a1);
            ldsm4(b0l, a0 + 256);  ldsm4(b1l, a1 + 256);

            mma16816(sf[0], qfh[ks], b0h + 0); mma16816(sf[1], qfh[ks], b0h + 2);
            mma16816(sf[2], qfh[ks], b1h + 0); mma16816(sf[3], qfh[ks], b1h + 2);
            mma16816(sf[0], qfh[ks], b0l + 0); mma16816(sf[1], qfh[ks], b0l + 2);
            mma16816(sf[2], qfh[ks], b1l + 0); mma16816(sf[3], qfh[ks], b1l + 2);
            mma16816(sf[0], qfl[ks], b0h + 0); mma16816(sf[1], qfl[ks], b0h + 2);
            mma16816(sf[2], qfl[ks], b1h + 0); mma16816(sf[3], qfl[ks], b1h + 2);
        }

        // ---- exp (prescaled), L accumulate, P -> smem fp16 ----
        {
            const int r0 = qg * 16 + g, r1 = r0 + 8;
#pragma unroll
            for (int nt = 0; nt < 4; nt++) {
                float e00 = __expf(sf[nt][0] - EXPC);
                float e01 = __expf(sf[nt][1] - EXPC);
                float e10 = __expf(sf[nt][2] - EXPC);
                float e11 = __expf(sf[nt][3] - EXPC);
                Lacc0 += e00 + e01;
                Lacc1 += e10 + e11;
                const int cbyte = (kg * 32 + nt * 8 + 2 * tq) * 2;
                *(uint32_t*)(sm + SM_P + r0 * VSTR + cbyte) = pack_f16x2(e00, e01);
                *(uint32_t*)(sm + SM_P + r1 * VSTR + cbyte) = pack_f16x2(e10, e11);
            }
        }
        __syncthreads();

        // ---- PV: O += P * V (single fp16 MMA) ----
#pragma unroll
        for (int kk = 0; kk < 4; kk++) {
            uint32_t ah[2][4];
#pragma unroll
            for (int mt = 0; mt < 2; mt++)
                ldsm4(ah[mt], smb + SM_P + (qg2 * 32 + mt * 16 + arow) * VSTR
                              + kk * 32 + akoff);
#pragma unroll
            for (int pp = 0; pp < 4; pp++) {
                uint32_t vv[4];
                ldsm4(vv, vcur + (cg * 64 + pp * 16 + rowp) * VSTR + kk * 32 + koff);
#pragma unroll
                for (int mt = 0; mt < 2; mt++) {
                    mma16816h(of[mt][2 * pp],     ah[mt], vv + 0);
                    mma16816h(of[mt][2 * pp + 1], ah[mt], vv + 2);
                }
            }
        }
    }

    // ---- L reduction + write L-partial ----
    Lacc0 += __shfl_xor_sync(0xffffffffu, Lacc0, 1);
    Lacc0 += __shfl_xor_sync(0xffffffffu, Lacc0, 2);
    Lacc1 += __shfl_xor_sync(0xffffffffu, Lacc1, 1);
    Lacc1 += __shfl_xor_sync(0xffffffffu, Lacc1, 2);
    float* Ls = (float*)(sm + SM_LS);
    if (tq == 0) {
        Ls[kg * 64 + qg * 16 + g]     = Lacc0;
        Ls[kg * 64 + qg * 16 + g + 8] = Lacc1;
    }
    __syncthreads();
    if (t < 64)
        g_Lp[((size_t)z * B_SZ + bb) * NTOK + n0 + t] = Ls[t] + Ls[64 + t];

    // ---- epilogue: stage unnormalized O[c][n], write O-partial ----
    {
        float* Osm = (float*)(sm + SM_OS);
        const int r0 = qg2 * 32 + g;
#pragma unroll
        for (int mt = 0; mt < 2; mt++) {
            const int ra = r0 + mt * 16, rb = ra + 8;
#pragma unroll
            for (int nt = 0; nt < 8; nt++) {
                const int c0 = cg * 64 + nt * 8 + 2 * tq;
                Osm[(c0)     * 68 + ra] = of[mt][nt][0];
                Osm[(c0 + 1) * 68 + ra] = of[mt][nt][1];
                Osm[(c0)     * 68 + rb] = of[mt][nt][2];
                Osm[(c0 + 1) * 68 + rb] = of[mt][nt][3];
            }
        }
    }
    __syncthreads();

    {
        const float* Osm = (const float*)(sm + SM_OS);
        float* ob = g_Op + ((size_t)z * B_SZ + bb) * CIN * NTOK + n0;
        for (int e = t; e < 256 * 16; e += 256) {
            int c = e >> 4, g4 = e & 15;
            *(float4*)(ob + (size_t)c * NTOK + g4 * 4) =
                *(const float4*)(Osm + c * 68 + g4 * 4);
        }
    }
}

// ---------------------------------------------------------------------------
// Kernel 4: combine  out[b][c][n] = (O0+O1) / (L0+L1)   (scale cancels)
// ---------------------------------------------------------------------------
__global__ __launch_bounds__(256) void combine_kernel(float* __restrict__ out)
{
    const size_t i4 = (size_t)blockIdx.x * 256 + threadIdx.x;
    const size_t e  = i4 * 4;
    const int n  = (int)(e & (NTOK - 1));
    const int bc = (int)(e >> 12);
    const int b  = bc >> 8;

    const float4 o0 = *(const float4*)(g_Op + e);
    const float4 o1 = *(const float4*)(g_Op + (size_t)B_SZ * CIN * NTOK + e);
    const float4 l0 = *(const float4*)(g_Lp + (size_t)b * NTOK + n);
    const float4 l1 = *(const float4*)(g_Lp + ((size_t)B_SZ + b) * NTOK + n);

    float4 r;
    r.x = (o0.x + o1.x) / (l0.x + l1.x);
    r.y = (o0.y + o1.y) / (l0.y + l1.y);
    r.z = (o0.z + o1.z) / (l0.z + l1.z);
    r.w = (o0.w + o1.w) / (l0.w + l1.w);
    *(float4*)(out + e) = r;
}

// ---------------------------------------------------------------------------
extern "C" void kernel_launch(void* const* d_in, const int* in_sizes, int n_in,
                              void* d_out, int out_size)
{
    const float* p   = (const float*)d_in[0];
    const float* bin = (const float*)d_in[1];
    const float* Wq  = (const float*)d_in[2];
    const float* bq  = (const float*)d_in[3];
    const float* Wk  = (const float*)d_in[4];
    const float* bk  = (const float*)d_in[5];
    float* out = (float*)d_out;

    cudaFuncSetAttribute(proj_mma_kernel, cudaFuncAttributeMaxDynamicSharedMemorySize,
                         PJ_SMEM);
    cudaFuncSetAttribute(attn_mma_kernel, cudaFuncAttributeMaxDynamicSharedMemorySize,
                         ATTN_SMEM);

    proj_mma_kernel<<<dim3(NTOK / 32, B_SZ, 2), 256, PJ_SMEM>>>(p, bin, Wq, bq, Wk, bk);
    vconv_kernel   <<<(B_SZ * CIN * NTOK) / (256 * 4), 256>>>(bin);
    attn_mma_kernel<<<dim3(NTOK / BM, B_SZ, NSPL), 256, ATTN_SMEM>>>();
    combine_kernel <<<(B_SZ * CIN * NTOK) / (256 * 4), 256>>>(out);
}